// round 3
// baseline (speedup 1.0000x reference)
#include <cuda_runtime.h>
#include <math.h>

// ---------------------------------------------------------------------------
// Problem constants (B=1 fixed)
// ---------------------------------------------------------------------------
#define T_SEQ 2048
#define C_EMB 4096
#define NH    32
#define NG    8
#define HS    128
#define QKV_N 6144          // (32 + 2*8) * 128
#define FFN_N 11008
#define EPS   1e-5f
#define SF    0.08838834764831845f   // 1/sqrt(128)

// ---------------------------------------------------------------------------
// Scratch (static __device__ arrays; no runtime allocation allowed)
// ---------------------------------------------------------------------------
static __device__ float g_n1     [T_SEQ * C_EMB];
static __device__ float g_qkv    [T_SEQ * QKV_N];
static __device__ float g_scaleS [T_SEQ * C_EMB];
static __device__ float g_scale_t[NH * T_SEQ];
static __device__ float g_q      [NH * T_SEQ * HS];
static __device__ float g_k      [NG * T_SEQ * HS];
static __device__ float g_v      [NG * T_SEQ * HS];
static __device__ float g_S      [(size_t)NH * T_SEQ * T_SEQ];  // 512 MB scores
static __device__ float g_y      [T_SEQ * C_EMB];
static __device__ float g_x2     [T_SEQ * C_EMB];
static __device__ float g_n2     [T_SEQ * C_EMB];
static __device__ float g_gate   [T_SEQ * FFN_N];
static __device__ float g_up     [T_SEQ * FFN_N];
static __device__ float g_act    [T_SEQ * FFN_N];

// ---------------------------------------------------------------------------
// Warp reduction helpers
// ---------------------------------------------------------------------------
__device__ __forceinline__ float warpReduceSum(float v) {
    #pragma unroll
    for (int o = 16; o > 0; o >>= 1) v += __shfl_xor_sync(0xffffffffu, v, o);
    return v;
}
__device__ __forceinline__ float warpReduceMax(float v) {
    #pragma unroll
    for (int o = 16; o > 0; o >>= 1) v = fmaxf(v, __shfl_xor_sync(0xffffffffu, v, o));
    return v;
}

// ---------------------------------------------------------------------------
// RMSNorm: one block per row of 4096
// ---------------------------------------------------------------------------
__global__ void rmsnorm_kernel(const float* __restrict__ x,
                               const float* __restrict__ w,
                               float* __restrict__ out) {
    int row = blockIdx.x;
    const float* xr = x + (size_t)row * C_EMB;
    float* orow = out + (size_t)row * C_EMB;
    int tid = threadIdx.x;

    float ss = 0.f;
    for (int i = tid; i < C_EMB; i += 256) {
        float v = xr[i];
        ss += v * v;
    }
    __shared__ float sm[8];
    __shared__ float s_inv;
    float w_sum = warpReduceSum(ss);
    if ((tid & 31) == 0) sm[tid >> 5] = w_sum;
    __syncthreads();
    if (tid == 0) {
        float tot = 0.f;
        #pragma unroll
        for (int i = 0; i < 8; i++) tot += sm[i];
        s_inv = rsqrtf(tot / (float)C_EMB + EPS);
    }
    __syncthreads();
    float inv = s_inv;
    for (int i = tid; i < C_EMB; i += 256)
        orow[i] = xr[i] * inv * w[i];
}

// ---------------------------------------------------------------------------
// Generic tiled SGEMM.
//   TRANSB = true : C[m][n] = sum_k A[m][k] * B[n][k]   (B is N x K row-major)
//   TRANSB = false: C[m][n] = sum_k A[m][k] * B[k][n]   (B is K x N row-major)
// Optional residual: C = result + Dres (same layout/ldc as C).
// Batched over blockIdx.z: A += z*sA; B += (z/bdiv)*sB; C += z*sC.
// REQUIRES: M % 128 == 0, N % 128 == 0, K % 8 == 0 (all call sites satisfy this).
// ---------------------------------------------------------------------------
#define BM 128
#define BN 128
#define BKK 8
template <bool TRANSB>
__global__ __launch_bounds__(256, 2)
void gemm_kernel(const float* __restrict__ A,
                 const float* __restrict__ B,
                 const float* __restrict__ Dres,
                 float* __restrict__ C,
                 int M, int N, int K,
                 int lda, int ldb, int ldc,
                 long long sA, long long sB, long long sC,
                 int bdiv) {
    __shared__ float As[BKK][BM];
    __shared__ float Bs[BKK][BN];

    int z = blockIdx.z;
    A += (long long)z * sA;
    B += (long long)(z / bdiv) * sB;
    C += (long long)z * sC;
    if (Dres) Dres += (long long)z * sC;

    int bm = blockIdx.y * BM;
    int bn = blockIdx.x * BN;
    int tid = threadIdx.x;

    // A tile load mapping: 128 rows x 8 k-cols, one float4 per thread
    int arow = tid >> 1;          // 0..127
    int acol = (tid & 1) << 2;    // 0 or 4
    const float* Ap = A + (size_t)(bm + arow) * lda + acol;

    const float* Bp;
    if (TRANSB) {
        Bp = B + (size_t)(bn + arow) * ldb + acol;    // same pattern, rows are n
    } else {
        Bp = B + (size_t)(tid >> 5) * ldb + bn + ((tid & 31) << 2); // k=tid/32, n=(tid%31... %32)*4
    }

    float acc[8][8];
    #pragma unroll
    for (int i = 0; i < 8; i++)
        #pragma unroll
        for (int j = 0; j < 8; j++) acc[i][j] = 0.f;

    int tm = (tid >> 4) << 3;   // 0..120
    int tn = (tid & 15) << 3;   // 0..120

    for (int k0 = 0; k0 < K; k0 += BKK) {
        float4 av = *(const float4*)(Ap + k0);
        As[acol + 0][arow] = av.x;
        As[acol + 1][arow] = av.y;
        As[acol + 2][arow] = av.z;
        As[acol + 3][arow] = av.w;
        if (TRANSB) {
            float4 bv = *(const float4*)(Bp + k0);
            Bs[acol + 0][arow] = bv.x;
            Bs[acol + 1][arow] = bv.y;
            Bs[acol + 2][arow] = bv.z;
            Bs[acol + 3][arow] = bv.w;
        } else {
            float4 bv = *(const float4*)(Bp + (size_t)k0 * ldb);
            *(float4*)&Bs[tid >> 5][(tid & 31) << 2] = bv;
        }
        __syncthreads();

        #pragma unroll
        for (int kk = 0; kk < BKK; kk++) {
            float4 a0 = *(const float4*)&As[kk][tm];
            float4 a1 = *(const float4*)&As[kk][tm + 4];
            float4 b0 = *(const float4*)&Bs[kk][tn];
            float4 b1 = *(const float4*)&Bs[kk][tn + 4];
            float a[8] = {a0.x, a0.y, a0.z, a0.w, a1.x, a1.y, a1.z, a1.w};
            float b[8] = {b0.x, b0.y, b0.z, b0.w, b1.x, b1.y, b1.z, b1.w};
            #pragma unroll
            for (int i = 0; i < 8; i++)
                #pragma unroll
                for (int j = 0; j < 8; j++)
                    acc[i][j] = fmaf(a[i], b[j], acc[i][j]);
        }
        __syncthreads();
    }

    #pragma unroll
    for (int i = 0; i < 8; i++) {
        size_t rowoff = (size_t)(bm + tm + i) * ldc + bn + tn;
        #pragma unroll
        for (int j = 0; j < 8; j++) {
            float v = acc[i][j];
            if (Dres) v += Dres[rowoff + j];
            C[rowoff + j] = v;
        }
    }
}

// ---------------------------------------------------------------------------
// QKV split + RoPE (rope covers the full 128-dim head here since ROPE_N==HS).
// qkv col c: g = c/768, slot = (c%768)/128, d = c%128.
//   slot<4 -> q head h=g*4+slot (rope), slot==4 -> k (rope), slot==5 -> v (raw)
// rotated[d] = (d<64) ? -x[d+64] : x[d-64];  out = x*cos + rotated*sin
// ---------------------------------------------------------------------------
__global__ void qkv_rope_split_kernel(const float* __restrict__ qkv,
                                      const float* __restrict__ cos_,
                                      const float* __restrict__ sin_,
                                      float* __restrict__ q,
                                      float* __restrict__ k,
                                      float* __restrict__ v) {
    int idx = blockIdx.x * 256 + threadIdx.x;
    if (idx >= T_SEQ * QKV_N) return;
    int t = idx / QKV_N;
    int c = idx - t * QKV_N;
    int g = c / (6 * HS);
    int rem = c - g * 6 * HS;
    int slot = rem / HS;
    int d = rem - slot * HS;

    float val = qkv[idx];
    if (slot < 5) {  // rope for q and k
        int headbase = idx - d;
        float partner = (d < 64) ? -qkv[headbase + d + 64] : qkv[headbase + d - 64];
        val = val * cos_[t * HS + d] + partner * sin_[t * HS + d];
    }
    if (slot < 4) {
        int h = g * 4 + slot;
        q[((size_t)h * T_SEQ + t) * HS + d] = val;
    } else if (slot == 4) {
        k[((size_t)g * T_SEQ + t) * HS + d] = val;
    } else {
        v[((size_t)g * T_SEQ + t) * HS + d] = val;
    }
}

// ---------------------------------------------------------------------------
// scale_t[h][t] = SF * mean_d relu(scaleS[t][h*128+d] + scale_b[h*128+d])
// One block (128 threads) per (h, t).
// ---------------------------------------------------------------------------
__global__ void scale_reduce_kernel(const float* __restrict__ S,
                                    const float* __restrict__ bias,
                                    float* __restrict__ scale_t) {
    int b = blockIdx.x;          // h * T_SEQ + t
    int h = b / T_SEQ;
    int t = b - h * T_SEQ;
    int d = threadIdx.x;         // 0..127
    int c = h * HS + d;
    float vv = fmaxf(S[(size_t)t * C_EMB + c] + bias[c], 0.f);

    __shared__ float sm[4];
    float ws = warpReduceSum(vv);
    if ((d & 31) == 0) sm[d >> 5] = ws;
    __syncthreads();
    if (d == 0) {
        float tot = sm[0] + sm[1] + sm[2] + sm[3];
        scale_t[b] = SF * (tot / (float)HS);
    }
}

// ---------------------------------------------------------------------------
// Softmax over rows of S (length 2048) with per-row scaling alpha.
// One block (256 threads, 8 elements/thread) per (h, t) row.
// ---------------------------------------------------------------------------
__global__ void softmax_kernel(float* __restrict__ S,
                               const float* __restrict__ scale_t) {
    size_t r = blockIdx.x;       // h * T_SEQ + t
    float alpha = scale_t[r];
    float* row = S + r * (size_t)T_SEQ;
    int tid = threadIdx.x;

    float vals[8];
    float m = -INFINITY;
    #pragma unroll
    for (int i = 0; i < 8; i++) {
        vals[i] = alpha * row[tid + 256 * i];
        m = fmaxf(m, vals[i]);
    }

    __shared__ float sm[8];
    __shared__ float s_bcast;
    float wm = warpReduceMax(m);
    if ((tid & 31) == 0) sm[tid >> 5] = wm;
    __syncthreads();
    if (tid == 0) {
        float mm = sm[0];
        #pragma unroll
        for (int i = 1; i < 8; i++) mm = fmaxf(mm, sm[i]);
        s_bcast = mm;
    }
    __syncthreads();
    m = s_bcast;

    float s = 0.f;
    #pragma unroll
    for (int i = 0; i < 8; i++) {
        vals[i] = __expf(vals[i] - m);
        s += vals[i];
    }
    __syncthreads();   // protect sm[] reuse
    float ws = warpReduceSum(s);
    if ((tid & 31) == 0) sm[tid >> 5] = ws;
    __syncthreads();
    if (tid == 0) {
        float tot = 0.f;
        #pragma unroll
        for (int i = 0; i < 8; i++) tot += sm[i];
        s_bcast = 1.f / tot;
    }
    __syncthreads();
    float inv = s_bcast;
    #pragma unroll
    for (int i = 0; i < 8; i++) row[tid + 256 * i] = vals[i] * inv;
}

// ---------------------------------------------------------------------------
// act = silu(gate) * up
// ---------------------------------------------------------------------------
__global__ void silu_mul_kernel(const float* __restrict__ g,
                                const float* __restrict__ u,
                                float* __restrict__ out, int n) {
    int idx = blockIdx.x * 256 + threadIdx.x;
    if (idx >= n) return;
    float x = g[idx];
    float sig = 1.f / (1.f + __expf(-x));
    out[idx] = x * sig * u[idx];
}

// ---------------------------------------------------------------------------
// Launch
// ---------------------------------------------------------------------------
extern "C" void kernel_launch(void* const* d_in, const int* in_sizes, int n_in,
                              void* d_out, int out_size) {
    const float* x       = (const float*)d_in[0];
    const float* cosp    = (const float*)d_in[1];
    const float* sinp    = (const float*)d_in[2];
    const float* norm1_w = (const float*)d_in[3];
    const float* norm2_w = (const float*)d_in[4];
    const float* attn_w  = (const float*)d_in[5];
    const float* proj_w  = (const float*)d_in[6];
    const float* scale_w = (const float*)d_in[7];
    const float* scale_b = (const float*)d_in[8];
    const float* gate_w  = (const float*)d_in[9];
    const float* up_w    = (const float*)d_in[10];
    const float* down_w  = (const float*)d_in[11];
    float* out = (float*)d_out;

    float *n1, *qkv, *scaleS, *scale_t, *q, *k, *v, *S, *y, *x2, *n2, *gate, *up, *act;
    cudaGetSymbolAddress((void**)&n1,      g_n1);
    cudaGetSymbolAddress((void**)&qkv,     g_qkv);
    cudaGetSymbolAddress((void**)&scaleS,  g_scaleS);
    cudaGetSymbolAddress((void**)&scale_t, g_scale_t);
    cudaGetSymbolAddress((void**)&q,       g_q);
    cudaGetSymbolAddress((void**)&k,       g_k);
    cudaGetSymbolAddress((void**)&v,       g_v);
    cudaGetSymbolAddress((void**)&S,       g_S);
    cudaGetSymbolAddress((void**)&y,       g_y);
    cudaGetSymbolAddress((void**)&x2,      g_x2);
    cudaGetSymbolAddress((void**)&n2,      g_n2);
    cudaGetSymbolAddress((void**)&gate,    g_gate);
    cudaGetSymbolAddress((void**)&up,      g_up);
    cudaGetSymbolAddress((void**)&act,     g_act);

    // 1. n1 = rmsnorm(x, norm1_w)
    rmsnorm_kernel<<<T_SEQ, 256>>>(x, norm1_w, n1);

    // 2. qkv = n1 @ attn_w^T          [2048 x 6144]
    gemm_kernel<true><<<dim3(QKV_N / BN, T_SEQ / BM, 1), 256>>>(
        n1, attn_w, nullptr, qkv, T_SEQ, QKV_N, C_EMB,
        C_EMB, C_EMB, QKV_N, 0, 0, 0, 1);

    // 3. scaleS = n1 @ scale_w^T      [2048 x 4096]
    gemm_kernel<true><<<dim3(C_EMB / BN, T_SEQ / BM, 1), 256>>>(
        n1, scale_w, nullptr, scaleS, T_SEQ, C_EMB, C_EMB,
        C_EMB, C_EMB, C_EMB, 0, 0, 0, 1);

    // 4. scale_t[h][t] = SF * mean relu(scaleS + b)
    scale_reduce_kernel<<<NH * T_SEQ, 128>>>(scaleS, scale_b, scale_t);

    // 5. split + rope
    qkv_rope_split_kernel<<<(T_SEQ * QKV_N + 255) / 256, 256>>>(qkv, cosp, sinp, q, k, v);

    // 6. scores: S[h] = q[h] @ k[h/4]^T    [2048 x 2048] x 32 heads
    gemm_kernel<true><<<dim3(T_SEQ / BN, T_SEQ / BM, NH), 256>>>(
        q, k, nullptr, S, T_SEQ, T_SEQ, HS,
        HS, HS, T_SEQ,
        (long long)T_SEQ * HS, (long long)T_SEQ * HS,
        (long long)T_SEQ * T_SEQ, 4);

    // 7. softmax with per-row temperature
    softmax_kernel<<<NH * T_SEQ, 256>>>(S, scale_t);

    // 8. y[:, h*128:(h+1)*128] = P[h] @ v[h/4]    (writes into [2048 x 4096])
    gemm_kernel<false><<<dim3(HS / BN, T_SEQ / BM, NH), 256>>>(
        S, v, nullptr, y, T_SEQ, HS, T_SEQ,
        T_SEQ, HS, C_EMB,
        (long long)T_SEQ * T_SEQ, (long long)T_SEQ * HS,
        (long long)HS, 4);

    // 9. x2 = x + y @ proj_w^T
    gemm_kernel<true><<<dim3(C_EMB / BN, T_SEQ / BM, 1), 256>>>(
        y, proj_w, x, x2, T_SEQ, C_EMB, C_EMB,
        C_EMB, C_EMB, C_EMB, 0, 0, 0, 1);

    // 10. n2 = rmsnorm(x2, norm2_w)
    rmsnorm_kernel<<<T_SEQ, 256>>>(x2, norm2_w, n2);

    // 11. gate = n2 @ gate_w^T        [2048 x 11008]
    gemm_kernel<true><<<dim3(FFN_N / BN, T_SEQ / BM, 1), 256>>>(
        n2, gate_w, nullptr, gate, T_SEQ, FFN_N, C_EMB,
        C_EMB, C_EMB, FFN_N, 0, 0, 0, 1);

    // 12. up = n2 @ up_w^T
    gemm_kernel<true><<<dim3(FFN_N / BN, T_SEQ / BM, 1), 256>>>(
        n2, up_w, nullptr, up, T_SEQ, FFN_N, C_EMB,
        C_EMB, C_EMB, FFN_N, 0, 0, 0, 1);

    // 13. act = silu(gate) * up
    silu_mul_kernel<<<(T_SEQ * FFN_N + 255) / 256, 256>>>(gate, up, act, T_SEQ * FFN_N);

    // 14. out = x2 + act @ down_w^T
    gemm_kernel<true><<<dim3(C_EMB / BN, T_SEQ / BM, 1), 256>>>(
        act, down_w, x2, out, T_SEQ, C_EMB, FFN_N,
        FFN_N, FFN_N, C_EMB, 0, 0, 0, 1);
}

// round 5
// speedup vs baseline: 1.3462x; 1.3462x over previous
#include <cuda_runtime.h>
#include <math.h>
#include <stdint.h>

// ---------------------------------------------------------------------------
// Problem constants (B=1 fixed)
// ---------------------------------------------------------------------------
#define T_SEQ 2048
#define C_EMB 4096
#define NH    32
#define NG    8
#define HS    128
#define QKV_N 6144          // (32 + 2*8) * 128
#define FFN_N 11008
#define EPS   1e-5f
#define SF    0.08838834764831845f   // 1/sqrt(128)

// ---------------------------------------------------------------------------
// Scratch (static __device__ arrays; no runtime allocation allowed)
// ---------------------------------------------------------------------------
static __device__ float g_n1     [T_SEQ * C_EMB];
static __device__ float g_qkv    [T_SEQ * QKV_N];
static __device__ float g_scaleS [T_SEQ * C_EMB];
static __device__ float g_scale_t[NH * T_SEQ];
static __device__ float g_q      [NH * T_SEQ * HS];
static __device__ float g_k      [NG * T_SEQ * HS];
static __device__ float g_vT     [NG * HS * T_SEQ];             // v transposed: [g][d][t]
static __device__ float g_S      [(size_t)NH * T_SEQ * T_SEQ];  // 512 MB scores
static __device__ float g_y      [T_SEQ * C_EMB];
static __device__ float g_x2     [T_SEQ * C_EMB];
static __device__ float g_n2     [T_SEQ * C_EMB];
static __device__ float g_gate   [T_SEQ * FFN_N];
static __device__ float g_up     [T_SEQ * FFN_N];
static __device__ float g_act    [T_SEQ * FFN_N];

// ---------------------------------------------------------------------------
// Warp reduction helpers
// ---------------------------------------------------------------------------
__device__ __forceinline__ float warpReduceSum(float v) {
    #pragma unroll
    for (int o = 16; o > 0; o >>= 1) v += __shfl_xor_sync(0xffffffffu, v, o);
    return v;
}
__device__ __forceinline__ float warpReduceMax(float v) {
    #pragma unroll
    for (int o = 16; o > 0; o >>= 1) v = fmaxf(v, __shfl_xor_sync(0xffffffffu, v, o));
    return v;
}

// ---------------------------------------------------------------------------
// RMSNorm: one block per row of 4096
// ---------------------------------------------------------------------------
__global__ void rmsnorm_kernel(const float* __restrict__ x,
                               const float* __restrict__ w,
                               float* __restrict__ out) {
    int row = blockIdx.x;
    const float* xr = x + (size_t)row * C_EMB;
    float* orow = out + (size_t)row * C_EMB;
    int tid = threadIdx.x;

    float ss = 0.f;
    for (int i = tid; i < C_EMB; i += 256) {
        float v = xr[i];
        ss += v * v;
    }
    __shared__ float sm[8];
    __shared__ float s_inv;
    float w_sum = warpReduceSum(ss);
    if ((tid & 31) == 0) sm[tid >> 5] = w_sum;
    __syncthreads();
    if (tid == 0) {
        float tot = 0.f;
        #pragma unroll
        for (int i = 0; i < 8; i++) tot += sm[i];
        s_inv = rsqrtf(tot / (float)C_EMB + EPS);
    }
    __syncthreads();
    float inv = s_inv;
    for (int i = tid; i < C_EMB; i += 256)
        orow[i] = xr[i] * inv * w[i];
}

// ---------------------------------------------------------------------------
// 3xTF32 tensor-core GEMM:  C[m][n] = sum_k A[m][k] * B[n][k]  (+ optional res)
// B is always N x K row-major ("TRANSB").  Batched over blockIdx.z.
// Block tile 128x128x16, 8 warps, warp tile 32x64, mma.sync m16n8k8 tf32.
// Accuracy: A,B split into hi/lo tf32; D += Ahi*Bhi + Alo*Bhi + Ahi*Blo.
// REQUIRES: M%128==0, N%128==0, K%16==0.
// ---------------------------------------------------------------------------
#define BM 128
#define BN 128
#define BK 16

__device__ __forceinline__ void split_tf32(float x, uint32_t& hi, uint32_t& lo) {
    uint32_t h;
    asm("cvt.rna.tf32.f32 %0, %1;" : "=r"(h) : "f"(x));
    hi = h;
    lo = __float_as_uint(x - __uint_as_float(h));
}

__device__ __forceinline__ void mma_tf32(float* c, const uint32_t* a, const uint32_t* b) {
    asm volatile(
        "mma.sync.aligned.m16n8k8.row.col.f32.tf32.tf32.f32 "
        "{%0,%1,%2,%3}, {%4,%5,%6,%7}, {%8,%9}, {%0,%1,%2,%3};\n"
        : "+f"(c[0]), "+f"(c[1]), "+f"(c[2]), "+f"(c[3])
        : "r"(a[0]), "r"(a[1]), "r"(a[2]), "r"(a[3]), "r"(b[0]), "r"(b[1]));
}

__global__ __launch_bounds__(256, 1)
void gemm_tf32(const float* __restrict__ A,
               const float* __restrict__ B,
               const float* __restrict__ Dres,
               float* __restrict__ C,
               int M, int N, int K,
               int lda, int ldb, int ldc,
               long long sA, long long sB, long long sC,
               int bdiv) {
    __shared__ float As[2][BM][BK + 4];
    __shared__ float Bs[2][BN][BK + 4];

    int z = blockIdx.z;
    A += (long long)z * sA;
    B += (long long)(z / bdiv) * sB;
    C += (long long)z * sC;
    if (Dres) Dres += (long long)z * sC;

    const int bm = blockIdx.y * BM;
    const int bn = blockIdx.x * BN;
    const int tid  = threadIdx.x;
    const int lane = tid & 31;
    const int warp = tid >> 5;
    const int wm = (warp & 3) * 32;   // warp m-offset within block tile
    const int wn = (warp >> 2) * 64;  // warp n-offset
    const int grp = lane >> 2;        // 0..7
    const int qid = lane & 3;         // 0..3

    // Global load mapping: 512 float4 per operand tile, 2 per thread.
    // idx = tid + 256*j : row = idx>>2 (0..127), kq = idx&3 (float4 within 16 k)
    const int r0 = tid >> 2;                 // row for j=0
    const int r1 = (tid + 256) >> 2;         // row for j=1
    const int kq0 = (tid & 3) * 4;
    const int kq1 = kq0;                     // (tid+256)&3 == tid&3

    const float* Ag0 = A + (size_t)(bm + r0) * lda + kq0;
    const float* Ag1 = A + (size_t)(bm + r1) * lda + kq1;
    const float* Bg0 = B + (size_t)(bn + r0) * ldb + kq0;
    const float* Bg1 = B + (size_t)(bn + r1) * ldb + kq1;

    float acc[2][8][4];
    #pragma unroll
    for (int mi = 0; mi < 2; mi++)
        #pragma unroll
        for (int nj = 0; nj < 8; nj++)
            #pragma unroll
            for (int q = 0; q < 4; q++) acc[mi][nj][q] = 0.f;

    const int nk = K / BK;

    // preload tile 0
    {
        float4 a0 = *(const float4*)(Ag0);
        float4 a1 = *(const float4*)(Ag1);
        float4 b0 = *(const float4*)(Bg0);
        float4 b1 = *(const float4*)(Bg1);
        *(float4*)&As[0][r0][kq0] = a0;
        *(float4*)&As[0][r1][kq1] = a1;
        *(float4*)&Bs[0][r0][kq0] = b0;
        *(float4*)&Bs[0][r1][kq1] = b1;
    }
    __syncthreads();

    for (int kt = 0; kt < nk; kt++) {
        const int cur = kt & 1;
        const int nxt = cur ^ 1;

        float4 pa0, pa1, pb0, pb1;
        const bool has_next = (kt + 1 < nk);
        if (has_next) {
            const int ko = (kt + 1) * BK;
            pa0 = *(const float4*)(Ag0 + ko);
            pa1 = *(const float4*)(Ag1 + ko);
            pb0 = *(const float4*)(Bg0 + ko);
            pb1 = *(const float4*)(Bg1 + ko);
        }

        #pragma unroll
        for (int kk = 0; kk < BK; kk += 8) {
            uint32_t ahi[2][4], alo[2][4], bhi[8][2], blo[8][2];
            #pragma unroll
            for (int mi = 0; mi < 2; mi++) {
                int mrow = wm + mi * 16;
                float a0 = As[cur][mrow + grp    ][kk + qid];
                float a1 = As[cur][mrow + 8 + grp][kk + qid];
                float a2 = As[cur][mrow + grp    ][kk + 4 + qid];
                float a3 = As[cur][mrow + 8 + grp][kk + 4 + qid];
                split_tf32(a0, ahi[mi][0], alo[mi][0]);
                split_tf32(a1, ahi[mi][1], alo[mi][1]);
                split_tf32(a2, ahi[mi][2], alo[mi][2]);
                split_tf32(a3, ahi[mi][3], alo[mi][3]);
            }
            #pragma unroll
            for (int nj = 0; nj < 8; nj++) {
                int nrow = wn + nj * 8;
                float b0 = Bs[cur][nrow + grp][kk + qid];
                float b1 = Bs[cur][nrow + grp][kk + 4 + qid];
                split_tf32(b0, bhi[nj][0], blo[nj][0]);
                split_tf32(b1, bhi[nj][1], blo[nj][1]);
            }
            // pass 1: hi*hi
            #pragma unroll
            for (int mi = 0; mi < 2; mi++)
                #pragma unroll
                for (int nj = 0; nj < 8; nj++)
                    mma_tf32(acc[mi][nj], ahi[mi], bhi[nj]);
            // pass 2: lo*hi
            #pragma unroll
            for (int mi = 0; mi < 2; mi++)
                #pragma unroll
                for (int nj = 0; nj < 8; nj++)
                    mma_tf32(acc[mi][nj], alo[mi], bhi[nj]);
            // pass 3: hi*lo
            #pragma unroll
            for (int mi = 0; mi < 2; mi++)
                #pragma unroll
                for (int nj = 0; nj < 8; nj++)
                    mma_tf32(acc[mi][nj], ahi[mi], blo[nj]);
        }

        if (has_next) {
            *(float4*)&As[nxt][r0][kq0] = pa0;
            *(float4*)&As[nxt][r1][kq1] = pa1;
            *(float4*)&Bs[nxt][r0][kq0] = pb0;
            *(float4*)&Bs[nxt][r1][kq1] = pb1;
        }
        __syncthreads();
    }

    // Epilogue: c0,c1 at (row, col), (row, col+1); c2,c3 at row+8.
    #pragma unroll
    for (int mi = 0; mi < 2; mi++) {
        #pragma unroll
        for (int nj = 0; nj < 8; nj++) {
            int row = bm + wm + mi * 16 + grp;
            int col = bn + wn + nj * 8 + qid * 2;
            size_t i0 = (size_t)row * ldc + col;
            size_t i1 = (size_t)(row + 8) * ldc + col;
            float v0 = acc[mi][nj][0], v1 = acc[mi][nj][1];
            float v2 = acc[mi][nj][2], v3 = acc[mi][nj][3];
            if (Dres) {
                v0 += Dres[i0];     v1 += Dres[i0 + 1];
                v2 += Dres[i1];     v3 += Dres[i1 + 1];
            }
            C[i0] = v0;  C[i0 + 1] = v1;
            C[i1] = v2;  C[i1 + 1] = v3;
        }
    }
}

// ---------------------------------------------------------------------------
// QKV split + RoPE. v is written TRANSPOSED: vT[g][d][t].
// qkv col c: g = c/768, slot = (c%768)/128, d = c%128.
//   slot<4 -> q head h=g*4+slot (rope), slot==4 -> k (rope), slot==5 -> vT (raw)
// ---------------------------------------------------------------------------
__global__ void qkv_rope_split_kernel(const float* __restrict__ qkv,
                                      const float* __restrict__ cos_,
                                      const float* __restrict__ sin_,
                                      float* __restrict__ q,
                                      float* __restrict__ k,
                                      float* __restrict__ vT) {
    int idx = blockIdx.x * 256 + threadIdx.x;
    if (idx >= T_SEQ * QKV_N) return;
    int t = idx / QKV_N;
    int c = idx - t * QKV_N;
    int g = c / (6 * HS);
    int rem = c - g * 6 * HS;
    int slot = rem / HS;
    int d = rem - slot * HS;

    float val = qkv[idx];
    if (slot < 5) {  // rope for q and k
        int headbase = idx - d;
        float partner = (d < 64) ? -qkv[headbase + d + 64] : qkv[headbase + d - 64];
        val = val * cos_[t * HS + d] + partner * sin_[t * HS + d];
    }
    if (slot < 4) {
        int h = g * 4 + slot;
        q[((size_t)h * T_SEQ + t) * HS + d] = val;
    } else if (slot == 4) {
        k[((size_t)g * T_SEQ + t) * HS + d] = val;
    } else {
        vT[((size_t)g * HS + d) * T_SEQ + t] = val;
    }
}

// ---------------------------------------------------------------------------
// scale_t[h][t] = SF * mean_d relu(scaleS[t][h*128+d] + scale_b[h*128+d])
// ---------------------------------------------------------------------------
__global__ void scale_reduce_kernel(const float* __restrict__ S,
                                    const float* __restrict__ bias,
                                    float* __restrict__ scale_t) {
    int b = blockIdx.x;          // h * T_SEQ + t
    int h = b / T_SEQ;
    int t = b - h * T_SEQ;
    int d = threadIdx.x;         // 0..127
    int c = h * HS + d;
    float vv = fmaxf(S[(size_t)t * C_EMB + c] + bias[c], 0.f);

    __shared__ float sm[4];
    float ws = warpReduceSum(vv);
    if ((d & 31) == 0) sm[d >> 5] = ws;
    __syncthreads();
    if (d == 0) {
        float tot = sm[0] + sm[1] + sm[2] + sm[3];
        scale_t[b] = SF * (tot / (float)HS);
    }
}

// ---------------------------------------------------------------------------
// Softmax over rows of S (length 2048) with per-row scaling alpha.
// ---------------------------------------------------------------------------
__global__ void softmax_kernel(float* __restrict__ S,
                               const float* __restrict__ scale_t) {
    size_t r = blockIdx.x;       // h * T_SEQ + t
    float alpha = scale_t[r];
    float* row = S + r * (size_t)T_SEQ;
    int tid = threadIdx.x;

    float vals[8];
    float m = -INFINITY;
    #pragma unroll
    for (int i = 0; i < 8; i++) {
        vals[i] = alpha * row[tid + 256 * i];
        m = fmaxf(m, vals[i]);
    }

    __shared__ float sm[8];
    __shared__ float s_bcast;
    float wm = warpReduceMax(m);
    if ((tid & 31) == 0) sm[tid >> 5] = wm;
    __syncthreads();
    if (tid == 0) {
        float mm = sm[0];
        #pragma unroll
        for (int i = 1; i < 8; i++) mm = fmaxf(mm, sm[i]);
        s_bcast = mm;
    }
    __syncthreads();
    m = s_bcast;

    float s = 0.f;
    #pragma unroll
    for (int i = 0; i < 8; i++) {
        vals[i] = __expf(vals[i] - m);
        s += vals[i];
    }
    __syncthreads();   // protect sm[] reuse
    float ws = warpReduceSum(s);
    if ((tid & 31) == 0) sm[tid >> 5] = ws;
    __syncthreads();
    if (tid == 0) {
        float tot = 0.f;
        #pragma unroll
        for (int i = 0; i < 8; i++) tot += sm[i];
        s_bcast = 1.f / tot;
    }
    __syncthreads();
    float inv = s_bcast;
    #pragma unroll
    for (int i = 0; i < 8; i++) row[tid + 256 * i] = vals[i] * inv;
}

// ---------------------------------------------------------------------------
// act = silu(gate) * up
// ---------------------------------------------------------------------------
__global__ void silu_mul_kernel(const float* __restrict__ g,
                                const float* __restrict__ u,
                                float* __restrict__ out, int n) {
    int idx = blockIdx.x * 256 + threadIdx.x;
    if (idx >= n) return;
    float x = g[idx];
    float sig = 1.f / (1.f + __expf(-x));
    out[idx] = x * sig * u[idx];
}

// ---------------------------------------------------------------------------
// Launch
// ---------------------------------------------------------------------------
extern "C" void kernel_launch(void* const* d_in, const int* in_sizes, int n_in,
                              void* d_out, int out_size) {
    const float* x       = (const float*)d_in[0];
    const float* cosp    = (const float*)d_in[1];
    const float* sinp    = (const float*)d_in[2];
    const float* norm1_w = (const float*)d_in[3];
    const float* norm2_w = (const float*)d_in[4];
    const float* attn_w  = (const float*)d_in[5];
    const float* proj_w  = (const float*)d_in[6];
    const float* scale_w = (const float*)d_in[7];
    const float* scale_b = (const float*)d_in[8];
    const float* gate_w  = (const float*)d_in[9];
    const float* up_w    = (const float*)d_in[10];
    const float* down_w  = (const float*)d_in[11];
    float* out = (float*)d_out;

    float *n1, *qkv, *scaleS, *scale_t, *q, *k, *vT, *S, *y, *x2, *n2, *gate, *up, *act;
    cudaGetSymbolAddress((void**)&n1,      g_n1);
    cudaGetSymbolAddress((void**)&qkv,     g_qkv);
    cudaGetSymbolAddress((void**)&scaleS,  g_scaleS);
    cudaGetSymbolAddress((void**)&scale_t, g_scale_t);
    cudaGetSymbolAddress((void**)&q,       g_q);
    cudaGetSymbolAddress((void**)&k,       g_k);
    cudaGetSymbolAddress((void**)&vT,      g_vT);
    cudaGetSymbolAddress((void**)&S,       g_S);
    cudaGetSymbolAddress((void**)&y,       g_y);
    cudaGetSymbolAddress((void**)&x2,      g_x2);
    cudaGetSymbolAddress((void**)&n2,      g_n2);
    cudaGetSymbolAddress((void**)&gate,    g_gate);
    cudaGetSymbolAddress((void**)&up,      g_up);
    cudaGetSymbolAddress((void**)&act,     g_act);

    // 1. n1 = rmsnorm(x, norm1_w)
    rmsnorm_kernel<<<T_SEQ, 256>>>(x, norm1_w, n1);

    // 2. qkv = n1 @ attn_w^T          [2048 x 6144]
    gemm_tf32<<<dim3(QKV_N / BN, T_SEQ / BM, 1), 256>>>(
        n1, attn_w, nullptr, qkv, T_SEQ, QKV_N, C_EMB,
        C_EMB, C_EMB, QKV_N, 0, 0, 0, 1);

    // 3. scaleS = n1 @ scale_w^T      [2048 x 4096]
    gemm_tf32<<<dim3(C_EMB / BN, T_SEQ / BM, 1), 256>>>(
        n1, scale_w, nullptr, scaleS, T_SEQ, C_EMB, C_EMB,
        C_EMB, C_EMB, C_EMB, 0, 0, 0, 1);

    // 4. scale_t[h][t] = SF * mean relu(scaleS + b)
    scale_reduce_kernel<<<NH * T_SEQ, 128>>>(scaleS, scale_b, scale_t);

    // 5. split + rope (+ v transpose)
    qkv_rope_split_kernel<<<(T_SEQ * QKV_N + 255) / 256, 256>>>(qkv, cosp, sinp, q, k, vT);

    // 6. scores: S[h] = q[h] @ k[h/4]^T    [2048 x 2048] x 32 heads
    gemm_tf32<<<dim3(T_SEQ / BN, T_SEQ / BM, NH), 256>>>(
        q, k, nullptr, S, T_SEQ, T_SEQ, HS,
        HS, HS, T_SEQ,
        (long long)T_SEQ * HS, (long long)T_SEQ * HS,
        (long long)T_SEQ * T_SEQ, 4);

    // 7. softmax with per-row temperature
    softmax_kernel<<<NH * T_SEQ, 256>>>(S, scale_t);

    // 8. y[:, h*128:(h+1)*128] = P[h] @ vT[h/4]^T  (B = vT is [d][t] = N x K)
    gemm_tf32<<<dim3(HS / BN, T_SEQ / BM, NH), 256>>>(
        S, vT, nullptr, y, T_SEQ, HS, T_SEQ,
        T_SEQ, T_SEQ, C_EMB,
        (long long)T_SEQ * T_SEQ, (long long)HS * T_SEQ,
        (long long)HS, 4);

    // 9. x2 = x + y @ proj_w^T
    gemm_tf32<<<dim3(C_EMB / BN, T_SEQ / BM, 1), 256>>>(
        y, proj_w, x, x2, T_SEQ, C_EMB, C_EMB,
        C_EMB, C_EMB, C_EMB, 0, 0, 0, 1);

    // 10. n2 = rmsnorm(x2, norm2_w)
    rmsnorm_kernel<<<T_SEQ, 256>>>(x2, norm2_w, n2);

    // 11. gate = n2 @ gate_w^T        [2048 x 11008]
    gemm_tf32<<<dim3(FFN_N / BN, T_SEQ / BM, 1), 256>>>(
        n2, gate_w, nullptr, gate, T_SEQ, FFN_N, C_EMB,
        C_EMB, C_EMB, FFN_N, 0, 0, 0, 1);

    // 12. up = n2 @ up_w^T
    gemm_tf32<<<dim3(FFN_N / BN, T_SEQ / BM, 1), 256>>>(
        n2, up_w, nullptr, up, T_SEQ, FFN_N, C_EMB,
        C_EMB, C_EMB, FFN_N, 0, 0, 0, 1);

    // 13. act = silu(gate) * up
    silu_mul_kernel<<<(T_SEQ * FFN_N + 255) / 256, 256>>>(gate, up, act, T_SEQ * FFN_N);

    // 14. out = x2 + act @ down_w^T
    gemm_tf32<<<dim3(C_EMB / BN, T_SEQ / BM, 1), 256>>>(
        act, down_w, x2, out, T_SEQ, C_EMB, FFN_N,
        FFN_N, FFN_N, C_EMB, 0, 0, 0, 1);
}

// round 6
// speedup vs baseline: 1.3468x; 1.0004x over previous
#include <cuda_runtime.h>
#include <math.h>
#include <stdint.h>

// ---------------------------------------------------------------------------
// Problem constants (B=1 fixed)
// ---------------------------------------------------------------------------
#define T_SEQ 2048
#define C_EMB 4096
#define NH    32
#define NG    8
#define HS    128
#define QKV_N 6144          // (32 + 2*8) * 128
#define FFN_N 11008
#define EPS   1e-5f
#define SF    0.08838834764831845f   // 1/sqrt(128)

// ---------------------------------------------------------------------------
// Scratch (static __device__ arrays; no runtime allocation allowed)
// ---------------------------------------------------------------------------
static __device__ float g_n1     [T_SEQ * C_EMB];
static __device__ float g_qkv    [T_SEQ * QKV_N];
static __device__ float g_scaleS [T_SEQ * C_EMB];
static __device__ float g_scale_t[NH * T_SEQ];
static __device__ float g_q      [NH * T_SEQ * HS];
static __device__ float g_k      [NG * T_SEQ * HS];
static __device__ float g_vT     [NG * HS * T_SEQ];             // v transposed: [g][d][t]
static __device__ float g_S      [(size_t)NH * T_SEQ * T_SEQ];  // 512 MB scores
static __device__ float g_y      [T_SEQ * C_EMB];
static __device__ float g_x2     [T_SEQ * C_EMB];
static __device__ float g_n2     [T_SEQ * C_EMB];
static __device__ float g_gate   [T_SEQ * FFN_N];
static __device__ float g_up     [T_SEQ * FFN_N];
static __device__ float g_act    [T_SEQ * FFN_N];

// ---------------------------------------------------------------------------
// Warp reduction helpers
// ---------------------------------------------------------------------------
__device__ __forceinline__ float warpReduceSum(float v) {
    #pragma unroll
    for (int o = 16; o > 0; o >>= 1) v += __shfl_xor_sync(0xffffffffu, v, o);
    return v;
}
__device__ __forceinline__ float warpReduceMax(float v) {
    #pragma unroll
    for (int o = 16; o > 0; o >>= 1) v = fmaxf(v, __shfl_xor_sync(0xffffffffu, v, o));
    return v;
}

// ---------------------------------------------------------------------------
// RMSNorm: one block per row of 4096
// ---------------------------------------------------------------------------
__global__ void rmsnorm_kernel(const float* __restrict__ x,
                               const float* __restrict__ w,
                               float* __restrict__ out) {
    int row = blockIdx.x;
    const float* xr = x + (size_t)row * C_EMB;
    float* orow = out + (size_t)row * C_EMB;
    int tid = threadIdx.x;

    float ss = 0.f;
    for (int i = tid; i < C_EMB; i += 256) {
        float v = xr[i];
        ss += v * v;
    }
    __shared__ float sm[8];
    __shared__ float s_inv;
    float w_sum = warpReduceSum(ss);
    if ((tid & 31) == 0) sm[tid >> 5] = w_sum;
    __syncthreads();
    if (tid == 0) {
        float tot = 0.f;
        #pragma unroll
        for (int i = 0; i < 8; i++) tot += sm[i];
        s_inv = rsqrtf(tot / (float)C_EMB + EPS);
    }
    __syncthreads();
    float inv = s_inv;
    for (int i = tid; i < C_EMB; i += 256)
        orow[i] = xr[i] * inv * w[i];
}

// ---------------------------------------------------------------------------
// 3xTF32 tensor-core GEMM:  C[m][n] = sum_k A[m][k] * B[n][k]  (+ optional res)
// B is always N x K row-major ("TRANSB").  Batched over blockIdx.z.
// Block tile 128x128x16, 8 warps, warp tile 32x64, mma.sync m16n8k8 tf32.
// Accuracy: A,B split into hi/lo tf32; D += Ahi*Bhi + Alo*Bhi + Ahi*Blo.
// REQUIRES: M%128==0, N%128==0, K%16==0.
// ---------------------------------------------------------------------------
#define BM 128
#define BN 128
#define BK 16

__device__ __forceinline__ void split_tf32(float x, uint32_t& hi, uint32_t& lo) {
    uint32_t h;
    asm("cvt.rna.tf32.f32 %0, %1;" : "=r"(h) : "f"(x));
    hi = h;
    lo = __float_as_uint(x - __uint_as_float(h));
}

__device__ __forceinline__ void mma_tf32(float* c, const uint32_t* a, const uint32_t* b) {
    asm volatile(
        "mma.sync.aligned.m16n8k8.row.col.f32.tf32.tf32.f32 "
        "{%0,%1,%2,%3}, {%4,%5,%6,%7}, {%8,%9}, {%0,%1,%2,%3};\n"
        : "+f"(c[0]), "+f"(c[1]), "+f"(c[2]), "+f"(c[3])
        : "r"(a[0]), "r"(a[1]), "r"(a[2]), "r"(a[3]), "r"(b[0]), "r"(b[1]));
}

__global__ __launch_bounds__(256, 1)
void gemm_tf32(const float* __restrict__ A,
               const float* __restrict__ B,
               const float* __restrict__ Dres,
               float* __restrict__ C,
               int M, int N, int K,
               int lda, int ldb, int ldc,
               long long sA, long long sB, long long sC,
               int bdiv) {
    __shared__ float As[2][BM][BK + 4];
    __shared__ float Bs[2][BN][BK + 4];

    int z = blockIdx.z;
    A += (long long)z * sA;
    B += (long long)(z / bdiv) * sB;
    C += (long long)z * sC;
    if (Dres) Dres += (long long)z * sC;

    const int bm = blockIdx.y * BM;
    const int bn = blockIdx.x * BN;
    const int tid  = threadIdx.x;
    const int lane = tid & 31;
    const int warp = tid >> 5;
    const int wm = (warp & 3) * 32;   // warp m-offset within block tile
    const int wn = (warp >> 2) * 64;  // warp n-offset
    const int grp = lane >> 2;        // 0..7
    const int qid = lane & 3;         // 0..3

    // Global load mapping: 512 float4 per operand tile, 2 per thread.
    // idx = tid + 256*j : row = idx>>2 (0..127), kq = idx&3 (float4 within 16 k)
    const int r0 = tid >> 2;                 // row for j=0
    const int r1 = (tid + 256) >> 2;         // row for j=1
    const int kq0 = (tid & 3) * 4;
    const int kq1 = kq0;                     // (tid+256)&3 == tid&3

    const float* Ag0 = A + (size_t)(bm + r0) * lda + kq0;
    const float* Ag1 = A + (size_t)(bm + r1) * lda + kq1;
    const float* Bg0 = B + (size_t)(bn + r0) * ldb + kq0;
    const float* Bg1 = B + (size_t)(bn + r1) * ldb + kq1;

    float acc[2][8][4];
    #pragma unroll
    for (int mi = 0; mi < 2; mi++)
        #pragma unroll
        for (int nj = 0; nj < 8; nj++)
            #pragma unroll
            for (int q = 0; q < 4; q++) acc[mi][nj][q] = 0.f;

    const int nk = K / BK;

    // preload tile 0
    {
        float4 a0 = *(const float4*)(Ag0);
        float4 a1 = *(const float4*)(Ag1);
        float4 b0 = *(const float4*)(Bg0);
        float4 b1 = *(const float4*)(Bg1);
        *(float4*)&As[0][r0][kq0] = a0;
        *(float4*)&As[0][r1][kq1] = a1;
        *(float4*)&Bs[0][r0][kq0] = b0;
        *(float4*)&Bs[0][r1][kq1] = b1;
    }
    __syncthreads();

    for (int kt = 0; kt < nk; kt++) {
        const int cur = kt & 1;
        const int nxt = cur ^ 1;

        float4 pa0, pa1, pb0, pb1;
        const bool has_next = (kt + 1 < nk);
        if (has_next) {
            const int ko = (kt + 1) * BK;
            pa0 = *(const float4*)(Ag0 + ko);
            pa1 = *(const float4*)(Ag1 + ko);
            pb0 = *(const float4*)(Bg0 + ko);
            pb1 = *(const float4*)(Bg1 + ko);
        }

        #pragma unroll
        for (int kk = 0; kk < BK; kk += 8) {
            uint32_t ahi[2][4], alo[2][4], bhi[8][2], blo[8][2];
            #pragma unroll
            for (int mi = 0; mi < 2; mi++) {
                int mrow = wm + mi * 16;
                float a0 = As[cur][mrow + grp    ][kk + qid];
                float a1 = As[cur][mrow + 8 + grp][kk + qid];
                float a2 = As[cur][mrow + grp    ][kk + 4 + qid];
                float a3 = As[cur][mrow + 8 + grp][kk + 4 + qid];
                split_tf32(a0, ahi[mi][0], alo[mi][0]);
                split_tf32(a1, ahi[mi][1], alo[mi][1]);
                split_tf32(a2, ahi[mi][2], alo[mi][2]);
                split_tf32(a3, ahi[mi][3], alo[mi][3]);
            }
            #pragma unroll
            for (int nj = 0; nj < 8; nj++) {
                int nrow = wn + nj * 8;
                float b0 = Bs[cur][nrow + grp][kk + qid];
                float b1 = Bs[cur][nrow + grp][kk + 4 + qid];
                split_tf32(b0, bhi[nj][0], blo[nj][0]);
                split_tf32(b1, bhi[nj][1], blo[nj][1]);
            }
            // pass 1: hi*hi
            #pragma unroll
            for (int mi = 0; mi < 2; mi++)
                #pragma unroll
                for (int nj = 0; nj < 8; nj++)
                    mma_tf32(acc[mi][nj], ahi[mi], bhi[nj]);
            // pass 2: lo*hi
            #pragma unroll
            for (int mi = 0; mi < 2; mi++)
                #pragma unroll
                for (int nj = 0; nj < 8; nj++)
                    mma_tf32(acc[mi][nj], alo[mi], bhi[nj]);
            // pass 3: hi*lo
            #pragma unroll
            for (int mi = 0; mi < 2; mi++)
                #pragma unroll
                for (int nj = 0; nj < 8; nj++)
                    mma_tf32(acc[mi][nj], ahi[mi], blo[nj]);
        }

        if (has_next) {
            *(float4*)&As[nxt][r0][kq0] = pa0;
            *(float4*)&As[nxt][r1][kq1] = pa1;
            *(float4*)&Bs[nxt][r0][kq0] = pb0;
            *(float4*)&Bs[nxt][r1][kq1] = pb1;
        }
        __syncthreads();
    }

    // Epilogue: c0,c1 at (row, col), (row, col+1); c2,c3 at row+8.
    #pragma unroll
    for (int mi = 0; mi < 2; mi++) {
        #pragma unroll
        for (int nj = 0; nj < 8; nj++) {
            int row = bm + wm + mi * 16 + grp;
            int col = bn + wn + nj * 8 + qid * 2;
            size_t i0 = (size_t)row * ldc + col;
            size_t i1 = (size_t)(row + 8) * ldc + col;
            float v0 = acc[mi][nj][0], v1 = acc[mi][nj][1];
            float v2 = acc[mi][nj][2], v3 = acc[mi][nj][3];
            if (Dres) {
                v0 += Dres[i0];     v1 += Dres[i0 + 1];
                v2 += Dres[i1];     v3 += Dres[i1 + 1];
            }
            C[i0] = v0;  C[i0 + 1] = v1;
            C[i1] = v2;  C[i1 + 1] = v3;
        }
    }
}

// ---------------------------------------------------------------------------
// QKV split + RoPE. v is written TRANSPOSED: vT[g][d][t].
// qkv col c: g = c/768, slot = (c%768)/128, d = c%128.
//   slot<4 -> q head h=g*4+slot (rope), slot==4 -> k (rope), slot==5 -> vT (raw)
// ---------------------------------------------------------------------------
__global__ void qkv_rope_split_kernel(const float* __restrict__ qkv,
                                      const float* __restrict__ cos_,
                                      const float* __restrict__ sin_,
                                      float* __restrict__ q,
                                      float* __restrict__ k,
                                      float* __restrict__ vT) {
    int idx = blockIdx.x * 256 + threadIdx.x;
    if (idx >= T_SEQ * QKV_N) return;
    int t = idx / QKV_N;
    int c = idx - t * QKV_N;
    int g = c / (6 * HS);
    int rem = c - g * 6 * HS;
    int slot = rem / HS;
    int d = rem - slot * HS;

    float val = qkv[idx];
    if (slot < 5) {  // rope for q and k
        int headbase = idx - d;
        float partner = (d < 64) ? -qkv[headbase + d + 64] : qkv[headbase + d - 64];
        val = val * cos_[t * HS + d] + partner * sin_[t * HS + d];
    }
    if (slot < 4) {
        int h = g * 4 + slot;
        q[((size_t)h * T_SEQ + t) * HS + d] = val;
    } else if (slot == 4) {
        k[((size_t)g * T_SEQ + t) * HS + d] = val;
    } else {
        vT[((size_t)g * HS + d) * T_SEQ + t] = val;
    }
}

// ---------------------------------------------------------------------------
// scale_t[h][t] = SF * mean_d relu(scaleS[t][h*128+d] + scale_b[h*128+d])
// ---------------------------------------------------------------------------
__global__ void scale_reduce_kernel(const float* __restrict__ S,
                                    const float* __restrict__ bias,
                                    float* __restrict__ scale_t) {
    int b = blockIdx.x;          // h * T_SEQ + t
    int h = b / T_SEQ;
    int t = b - h * T_SEQ;
    int d = threadIdx.x;         // 0..127
    int c = h * HS + d;
    float vv = fmaxf(S[(size_t)t * C_EMB + c] + bias[c], 0.f);

    __shared__ float sm[4];
    float ws = warpReduceSum(vv);
    if ((d & 31) == 0) sm[d >> 5] = ws;
    __syncthreads();
    if (d == 0) {
        float tot = sm[0] + sm[1] + sm[2] + sm[3];
        scale_t[b] = SF * (tot / (float)HS);
    }
}

// ---------------------------------------------------------------------------
// Softmax over rows of S (length 2048) with per-row scaling alpha.
// ---------------------------------------------------------------------------
__global__ void softmax_kernel(float* __restrict__ S,
                               const float* __restrict__ scale_t) {
    size_t r = blockIdx.x;       // h * T_SEQ + t
    float alpha = scale_t[r];
    float* row = S + r * (size_t)T_SEQ;
    int tid = threadIdx.x;

    float vals[8];
    float m = -INFINITY;
    #pragma unroll
    for (int i = 0; i < 8; i++) {
        vals[i] = alpha * row[tid + 256 * i];
        m = fmaxf(m, vals[i]);
    }

    __shared__ float sm[8];
    __shared__ float s_bcast;
    float wm = warpReduceMax(m);
    if ((tid & 31) == 0) sm[tid >> 5] = wm;
    __syncthreads();
    if (tid == 0) {
        float mm = sm[0];
        #pragma unroll
        for (int i = 1; i < 8; i++) mm = fmaxf(mm, sm[i]);
        s_bcast = mm;
    }
    __syncthreads();
    m = s_bcast;

    float s = 0.f;
    #pragma unroll
    for (int i = 0; i < 8; i++) {
        vals[i] = __expf(vals[i] - m);
        s += vals[i];
    }
    __syncthreads();   // protect sm[] reuse
    float ws = warpReduceSum(s);
    if ((tid & 31) == 0) sm[tid >> 5] = ws;
    __syncthreads();
    if (tid == 0) {
        float tot = 0.f;
        #pragma unroll
        for (int i = 0; i < 8; i++) tot += sm[i];
        s_bcast = 1.f / tot;
    }
    __syncthreads();
    float inv = s_bcast;
    #pragma unroll
    for (int i = 0; i < 8; i++) row[tid + 256 * i] = vals[i] * inv;
}

// ---------------------------------------------------------------------------
// act = silu(gate) * up
// ---------------------------------------------------------------------------
__global__ void silu_mul_kernel(const float* __restrict__ g,
                                const float* __restrict__ u,
                                float* __restrict__ out, int n) {
    int idx = blockIdx.x * 256 + threadIdx.x;
    if (idx >= n) return;
    float x = g[idx];
    float sig = 1.f / (1.f + __expf(-x));
    out[idx] = x * sig * u[idx];
}

// ---------------------------------------------------------------------------
// Launch
// ---------------------------------------------------------------------------
extern "C" void kernel_launch(void* const* d_in, const int* in_sizes, int n_in,
                              void* d_out, int out_size) {
    const float* x       = (const float*)d_in[0];
    const float* cosp    = (const float*)d_in[1];
    const float* sinp    = (const float*)d_in[2];
    const float* norm1_w = (const float*)d_in[3];
    const float* norm2_w = (const float*)d_in[4];
    const float* attn_w  = (const float*)d_in[5];
    const float* proj_w  = (const float*)d_in[6];
    const float* scale_w = (const float*)d_in[7];
    const float* scale_b = (const float*)d_in[8];
    const float* gate_w  = (const float*)d_in[9];
    const float* up_w    = (const float*)d_in[10];
    const float* down_w  = (const float*)d_in[11];
    float* out = (float*)d_out;

    float *n1, *qkv, *scaleS, *scale_t, *q, *k, *vT, *S, *y, *x2, *n2, *gate, *up, *act;
    cudaGetSymbolAddress((void**)&n1,      g_n1);
    cudaGetSymbolAddress((void**)&qkv,     g_qkv);
    cudaGetSymbolAddress((void**)&scaleS,  g_scaleS);
    cudaGetSymbolAddress((void**)&scale_t, g_scale_t);
    cudaGetSymbolAddress((void**)&q,       g_q);
    cudaGetSymbolAddress((void**)&k,       g_k);
    cudaGetSymbolAddress((void**)&vT,      g_vT);
    cudaGetSymbolAddress((void**)&S,       g_S);
    cudaGetSymbolAddress((void**)&y,       g_y);
    cudaGetSymbolAddress((void**)&x2,      g_x2);
    cudaGetSymbolAddress((void**)&n2,      g_n2);
    cudaGetSymbolAddress((void**)&gate,    g_gate);
    cudaGetSymbolAddress((void**)&up,      g_up);
    cudaGetSymbolAddress((void**)&act,     g_act);

    // 1. n1 = rmsnorm(x, norm1_w)
    rmsnorm_kernel<<<T_SEQ, 256>>>(x, norm1_w, n1);

    // 2. qkv = n1 @ attn_w^T          [2048 x 6144]
    gemm_tf32<<<dim3(QKV_N / BN, T_SEQ / BM, 1), 256>>>(
        n1, attn_w, nullptr, qkv, T_SEQ, QKV_N, C_EMB,
        C_EMB, C_EMB, QKV_N, 0, 0, 0, 1);

    // 3. scaleS = n1 @ scale_w^T      [2048 x 4096]
    gemm_tf32<<<dim3(C_EMB / BN, T_SEQ / BM, 1), 256>>>(
        n1, scale_w, nullptr, scaleS, T_SEQ, C_EMB, C_EMB,
        C_EMB, C_EMB, C_EMB, 0, 0, 0, 1);

    // 4. scale_t[h][t] = SF * mean relu(scaleS + b)
    scale_reduce_kernel<<<NH * T_SEQ, 128>>>(scaleS, scale_b, scale_t);

    // 5. split + rope (+ v transpose)
    qkv_rope_split_kernel<<<(T_SEQ * QKV_N + 255) / 256, 256>>>(qkv, cosp, sinp, q, k, vT);

    // 6. scores: S[h] = q[h] @ k[h/4]^T    [2048 x 2048] x 32 heads
    gemm_tf32<<<dim3(T_SEQ / BN, T_SEQ / BM, NH), 256>>>(
        q, k, nullptr, S, T_SEQ, T_SEQ, HS,
        HS, HS, T_SEQ,
        (long long)T_SEQ * HS, (long long)T_SEQ * HS,
        (long long)T_SEQ * T_SEQ, 4);

    // 7. softmax with per-row temperature
    softmax_kernel<<<NH * T_SEQ, 256>>>(S, scale_t);

    // 8. y[:, h*128:(h+1)*128] = P[h] @ vT[h/4]^T  (B = vT is [d][t] = N x K)
    gemm_tf32<<<dim3(HS / BN, T_SEQ / BM, NH), 256>>>(
        S, vT, nullptr, y, T_SEQ, HS, T_SEQ,
        T_SEQ, T_SEQ, C_EMB,
        (long long)T_SEQ * T_SEQ, (long long)HS * T_SEQ,
        (long long)HS, 4);

    // 9. x2 = x + y @ proj_w^T
    gemm_tf32<<<dim3(C_EMB / BN, T_SEQ / BM, 1), 256>>>(
        y, proj_w, x, x2, T_SEQ, C_EMB, C_EMB,
        C_EMB, C_EMB, C_EMB, 0, 0, 0, 1);

    // 10. n2 = rmsnorm(x2, norm2_w)
    rmsnorm_kernel<<<T_SEQ, 256>>>(x2, norm2_w, n2);

    // 11. gate = n2 @ gate_w^T        [2048 x 11008]
    gemm_tf32<<<dim3(FFN_N / BN, T_SEQ / BM, 1), 256>>>(
        n2, gate_w, nullptr, gate, T_SEQ, FFN_N, C_EMB,
        C_EMB, C_EMB, FFN_N, 0, 0, 0, 1);

    // 12. up = n2 @ up_w^T
    gemm_tf32<<<dim3(FFN_N / BN, T_SEQ / BM, 1), 256>>>(
        n2, up_w, nullptr, up, T_SEQ, FFN_N, C_EMB,
        C_EMB, C_EMB, FFN_N, 0, 0, 0, 1);

    // 13. act = silu(gate) * up
    silu_mul_kernel<<<(T_SEQ * FFN_N + 255) / 256, 256>>>(gate, up, act, T_SEQ * FFN_N);

    // 14. out = x2 + act @ down_w^T
    gemm_tf32<<<dim3(C_EMB / BN, T_SEQ / BM, 1), 256>>>(
        act, down_w, x2, out, T_SEQ, C_EMB, FFN_N,
        FFN_N, FFN_N, C_EMB, 0, 0, 0, 1);
}

// round 11
// speedup vs baseline: 1.4371x; 1.0671x over previous
#include <cuda_runtime.h>
#include <math.h>
#include <stdint.h>

#define T_SEQ 2048
#define C_EMB 4096
#define NH    32
#define NG    8
#define HS    128
#define QKV_N 6144
#define FFN_N 11008
#define EPS   1e-5f
#define SF    0.08838834764831845f

static __device__ float g_n1     [T_SEQ * C_EMB];
static __device__ float g_qkv    [T_SEQ * QKV_N];
static __device__ float g_scaleS [T_SEQ * C_EMB];
static __device__ float g_scale_t[NH * T_SEQ];
static __device__ float g_q      [NH * T_SEQ * HS];
static __device__ float g_k      [NG * T_SEQ * HS];
static __device__ float g_vT     [NG * HS * T_SEQ];
static __device__ float g_S      [(size_t)NH * T_SEQ * T_SEQ];
static __device__ float g_y      [T_SEQ * C_EMB];
static __device__ float g_x2     [T_SEQ * C_EMB];
static __device__ float g_n2     [T_SEQ * C_EMB];
static __device__ float g_gate   [T_SEQ * FFN_N];
static __device__ float g_up     [T_SEQ * FFN_N];
static __device__ float g_act    [T_SEQ * FFN_N];

__device__ __forceinline__ float warpReduceSum(float v) {
    #pragma unroll
    for (int o = 16; o > 0; o >>= 1) v += __shfl_xor_sync(0xffffffffu, v, o);
    return v;
}
__device__ __forceinline__ float warpReduceMax(float v) {
    #pragma unroll
    for (int o = 16; o > 0; o >>= 1) v = fmaxf(v, __shfl_xor_sync(0xffffffffu, v, o));
    return v;
}

// ---------------------------------------------------------------------------
// rmsnorm
// ---------------------------------------------------------------------------
__global__ void rmsnorm_kernel(const float* __restrict__ x,
                               const float* __restrict__ w,
                               float* __restrict__ out) {
    int row = blockIdx.x;
    const float* xr = x + (size_t)row * C_EMB;
    float* orow = out + (size_t)row * C_EMB;
    int tid = threadIdx.x;
    float ss = 0.f;
    for (int i = tid; i < C_EMB; i += 256) { float v = xr[i]; ss += v * v; }
    __shared__ float sm[8];
    __shared__ float s_inv;
    float ws = warpReduceSum(ss);
    if ((tid & 31) == 0) sm[tid >> 5] = ws;
    __syncthreads();
    if (tid == 0) {
        float tot = 0.f;
        #pragma unroll
        for (int i = 0; i < 8; i++) tot += sm[i];
        s_inv = rsqrtf(tot / (float)C_EMB + EPS);
    }
    __syncthreads();
    float inv = s_inv;
    for (int i = tid; i < C_EMB; i += 256) orow[i] = xr[i] * inv * w[i];
}

// ---------------------------------------------------------------------------
// 3xBF16 split GEMM on legacy mma pipe: C[m][n] = sum_k A[m][k]*B[n][k] (+res)
// Block tile 128x128x16, 8 warps, warp tile 32x64, mma.m16n8k16.bf16.
// fp32 -> (hi,lo) bf16 split at smem-fill; passes hh, lh, hl.
// REQUIRES M%128==0, N%128==0, K%16==0.
// ---------------------------------------------------------------------------
#define BM 128
#define BN 128
#define BK 16
#define PITCH 24   // bf16 elements per smem row (48B, conflict-free for 12r mod 32)

__device__ __forceinline__ void split2(float x0, float x1, uint32_t& h, uint32_t& l) {
    // h = {bf16(x1), bf16(x0)} (x0 in low half), l = residual pair
    asm("cvt.rn.bf16x2.f32 %0, %1, %2;" : "=r"(h) : "f"(x1), "f"(x0));
    float f0 = __uint_as_float(h << 16);
    float f1 = __uint_as_float(h & 0xffff0000u);
    asm("cvt.rn.bf16x2.f32 %0, %1, %2;" : "=r"(l) : "f"(x1 - f1), "f"(x0 - f0));
}
__device__ __forceinline__ void mma_bf16(float* c, const uint32_t* a, const uint32_t* b) {
    asm volatile(
        "mma.sync.aligned.m16n8k16.row.col.f32.bf16.bf16.f32 "
        "{%0,%1,%2,%3}, {%4,%5,%6,%7}, {%8,%9}, {%0,%1,%2,%3};\n"
        : "+f"(c[0]), "+f"(c[1]), "+f"(c[2]), "+f"(c[3])
        : "r"(a[0]), "r"(a[1]), "r"(a[2]), "r"(a[3]), "r"(b[0]), "r"(b[1]));
}

__global__ __launch_bounds__(256, 1)
void gemm_bf3(const float* __restrict__ A,
              const float* __restrict__ B,
              const float* __restrict__ Dres,
              float* __restrict__ C,
              int K, int lda, int ldb, int ldc,
              long long sA, long long sB, long long sC, int bdiv) {
    // tiles: 0=Ah 1=Al 2=Bh 3=Bl ; 2 buffers ; 49152 bytes total (= 48KB limit)
    __shared__ __align__(16) uint16_t smt[2][4][BM][PITCH];

    int z = blockIdx.z;
    A += (long long)z * sA;
    B += (long long)(z / bdiv) * sB;
    C += (long long)z * sC;
    if (Dres) Dres += (long long)z * sC;

    const int bm = blockIdx.y * BM;
    const int bn = blockIdx.x * BN;
    const int tid  = threadIdx.x;
    const int lane = tid & 31;
    const int warp = tid >> 5;
    const int wm = (warp & 3) * 32;
    const int wn = (warp >> 2) * 64;
    const int grp = lane >> 2;   // 0..7
    const int qid = lane & 3;    // 0..3

    // fill mapping: 512 float4 per matrix tile; this thread handles rows
    // frow0 (=tid/4) and frow1 (=frow0+64), float4 col fkq.
    const int frow0 = tid >> 2;
    const int frow1 = frow0 + 64;
    const int fkq   = (tid & 3) * 4;

    const float* Ag0 = A + (size_t)(bm + frow0) * lda + fkq;
    const float* Ag1 = A + (size_t)(bm + frow1) * lda + fkq;
    const float* Bg0 = B + (size_t)(bn + frow0) * ldb + fkq;
    const float* Bg1 = B + (size_t)(bn + frow1) * ldb + fkq;

    float acc[2][8][4];
    #pragma unroll
    for (int mi = 0; mi < 2; mi++)
        #pragma unroll
        for (int nj = 0; nj < 8; nj++)
            #pragma unroll
            for (int q = 0; q < 4; q++) acc[mi][nj][q] = 0.f;

    const int nk = K / BK;

    #define STORE4(buf, th, tl, row, v) do {                                   \
        uint32_t _h0, _l0, _h1, _l1;                                           \
        split2((v).x, (v).y, _h0, _l0);                                        \
        split2((v).z, (v).w, _h1, _l1);                                        \
        *(uint64_t*)&smt[buf][th][row][fkq] = ((uint64_t)_h1 << 32) | _h0;     \
        *(uint64_t*)&smt[buf][tl][row][fkq] = ((uint64_t)_l1 << 32) | _l0;     \
    } while (0)

    // preload + store chunk 0
    {
        float4 a0 = *(const float4*)(Ag0);
        float4 a1 = *(const float4*)(Ag1);
        float4 b0 = *(const float4*)(Bg0);
        float4 b1 = *(const float4*)(Bg1);
        STORE4(0, 0, 1, frow0, a0);
        STORE4(0, 0, 1, frow1, a1);
        STORE4(0, 2, 3, frow0, b0);
        STORE4(0, 2, 3, frow1, b1);
    }
    __syncthreads();

    for (int kt = 0; kt < nk; kt++) {
        const int cur = kt & 1;
        const int nxt = cur ^ 1;
        const bool has_next = (kt + 1 < nk);

        float4 pa0, pa1, pb0, pb1;
        if (has_next) {
            const int ko = (kt + 1) * BK;
            pa0 = *(const float4*)(Ag0 + ko);
            pa1 = *(const float4*)(Ag1 + ko);
            pb0 = *(const float4*)(Bg0 + ko);
            pb1 = *(const float4*)(Bg1 + ko);
        }

        // load fragments (scalar LDS.32, conflict-free)
        uint32_t ah[2][4], al[2][4], bh[8][2], bl[8][2];
        #pragma unroll
        for (int mi = 0; mi < 2; mi++) {
            int m0 = wm + mi * 16 + grp;
            int m1 = m0 + 8;
            int k0 = 2 * qid, k1 = 8 + 2 * qid;
            ah[mi][0] = *(const uint32_t*)&smt[cur][0][m0][k0];
            ah[mi][1] = *(const uint32_t*)&smt[cur][0][m1][k0];
            ah[mi][2] = *(const uint32_t*)&smt[cur][0][m0][k1];
            ah[mi][3] = *(const uint32_t*)&smt[cur][0][m1][k1];
            al[mi][0] = *(const uint32_t*)&smt[cur][1][m0][k0];
            al[mi][1] = *(const uint32_t*)&smt[cur][1][m1][k0];
            al[mi][2] = *(const uint32_t*)&smt[cur][1][m0][k1];
            al[mi][3] = *(const uint32_t*)&smt[cur][1][m1][k1];
        }
        #pragma unroll
        for (int nj = 0; nj < 8; nj++) {
            int n = wn + nj * 8 + grp;
            int k0 = 2 * qid, k1 = 8 + 2 * qid;
            bh[nj][0] = *(const uint32_t*)&smt[cur][2][n][k0];
            bh[nj][1] = *(const uint32_t*)&smt[cur][2][n][k1];
            bl[nj][0] = *(const uint32_t*)&smt[cur][3][n][k0];
            bl[nj][1] = *(const uint32_t*)&smt[cur][3][n][k1];
        }

        // pass 1: hi*hi
        #pragma unroll
        for (int mi = 0; mi < 2; mi++)
            #pragma unroll
            for (int nj = 0; nj < 8; nj++)
                mma_bf16(acc[mi][nj], ah[mi], bh[nj]);
        // pass 2: lo*hi
        #pragma unroll
        for (int mi = 0; mi < 2; mi++)
            #pragma unroll
            for (int nj = 0; nj < 8; nj++)
                mma_bf16(acc[mi][nj], al[mi], bh[nj]);
        // pass 3: hi*lo
        #pragma unroll
        for (int mi = 0; mi < 2; mi++)
            #pragma unroll
            for (int nj = 0; nj < 8; nj++)
                mma_bf16(acc[mi][nj], ah[mi], bl[nj]);

        if (has_next) {
            STORE4(nxt, 0, 1, frow0, pa0);
            STORE4(nxt, 0, 1, frow1, pa1);
            STORE4(nxt, 2, 3, frow0, pb0);
            STORE4(nxt, 2, 3, frow1, pb1);
        }
        __syncthreads();
    }

    #pragma unroll
    for (int mi = 0; mi < 2; mi++) {
        #pragma unroll
        for (int nj = 0; nj < 8; nj++) {
            int row = bm + wm + mi * 16 + grp;
            int col = bn + wn + nj * 8 + qid * 2;
            size_t i0 = (size_t)row * ldc + col;
            size_t i1 = (size_t)(row + 8) * ldc + col;
            float v0 = acc[mi][nj][0], v1 = acc[mi][nj][1];
            float v2 = acc[mi][nj][2], v3 = acc[mi][nj][3];
            if (Dres) {
                v0 += Dres[i0]; v1 += Dres[i0 + 1];
                v2 += Dres[i1]; v3 += Dres[i1 + 1];
            }
            C[i0] = v0; C[i0 + 1] = v1;
            C[i1] = v2; C[i1 + 1] = v3;
        }
    }
}

// ---------------------------------------------------------------------------
// qkv split + rope (v transposed)
// ---------------------------------------------------------------------------
__global__ void qkv_rope_split_kernel(const float* __restrict__ qkv,
                                      const float* __restrict__ cos_,
                                      const float* __restrict__ sin_,
                                      float* __restrict__ q,
                                      float* __restrict__ k,
                                      float* __restrict__ vT) {
    int idx = blockIdx.x * 256 + threadIdx.x;
    if (idx >= T_SEQ * QKV_N) return;
    int t = idx / QKV_N;
    int c = idx - t * QKV_N;
    int g = c / (6 * HS);
    int rem = c - g * 6 * HS;
    int slot = rem / HS;
    int d = rem - slot * HS;
    float val = qkv[idx];
    if (slot < 5) {
        int hb = idx - d;
        float partner = (d < 64) ? -qkv[hb + d + 64] : qkv[hb + d - 64];
        val = val * cos_[t * HS + d] + partner * sin_[t * HS + d];
    }
    if (slot < 4)       q[((size_t)(g * 4 + slot) * T_SEQ + t) * HS + d] = val;
    else if (slot == 4) k[((size_t)g * T_SEQ + t) * HS + d] = val;
    else                vT[((size_t)g * HS + d) * T_SEQ + t] = val;
}

__global__ void scale_reduce_kernel(const float* __restrict__ S,
                                    const float* __restrict__ bias,
                                    float* __restrict__ scale_t) {
    int b = blockIdx.x;
    int h = b / T_SEQ;
    int t = b - h * T_SEQ;
    int d = threadIdx.x;
    int c = h * HS + d;
    float vv = fmaxf(S[(size_t)t * C_EMB + c] + bias[c], 0.f);
    __shared__ float sm[4];
    float ws = warpReduceSum(vv);
    if ((d & 31) == 0) sm[d >> 5] = ws;
    __syncthreads();
    if (d == 0) scale_t[b] = SF * ((sm[0] + sm[1] + sm[2] + sm[3]) / (float)HS);
}

__global__ void softmax_kernel(float* __restrict__ S,
                               const float* __restrict__ scale_t) {
    size_t r = blockIdx.x;
    float alpha = scale_t[r];
    float* row = S + r * (size_t)T_SEQ;
    int tid = threadIdx.x;
    float vals[8];
    float m = -INFINITY;
    #pragma unroll
    for (int i = 0; i < 8; i++) {
        vals[i] = alpha * row[tid + 256 * i];
        m = fmaxf(m, vals[i]);
    }
    __shared__ float sm[8];
    __shared__ float s_b;
    float wm = warpReduceMax(m);
    if ((tid & 31) == 0) sm[tid >> 5] = wm;
    __syncthreads();
    if (tid == 0) {
        float mm = sm[0];
        #pragma unroll
        for (int i = 1; i < 8; i++) mm = fmaxf(mm, sm[i]);
        s_b = mm;
    }
    __syncthreads();
    m = s_b;
    float s = 0.f;
    #pragma unroll
    for (int i = 0; i < 8; i++) { vals[i] = __expf(vals[i] - m); s += vals[i]; }
    __syncthreads();
    float ws = warpReduceSum(s);
    if ((tid & 31) == 0) sm[tid >> 5] = ws;
    __syncthreads();
    if (tid == 0) {
        float tot = 0.f;
        #pragma unroll
        for (int i = 0; i < 8; i++) tot += sm[i];
        s_b = 1.f / tot;
    }
    __syncthreads();
    float inv = s_b;
    #pragma unroll
    for (int i = 0; i < 8; i++) row[tid + 256 * i] = vals[i] * inv;
}

__global__ void silu_mul_kernel(const float* __restrict__ g,
                                const float* __restrict__ u,
                                float* __restrict__ out, int n) {
    int idx = blockIdx.x * 256 + threadIdx.x;
    if (idx >= n) return;
    float x = g[idx];
    out[idx] = x / (1.f + __expf(-x)) * u[idx];
}

// ---------------------------------------------------------------------------
extern "C" void kernel_launch(void* const* d_in, const int* in_sizes, int n_in,
                              void* d_out, int out_size) {
    const float* x       = (const float*)d_in[0];
    const float* cosp    = (const float*)d_in[1];
    const float* sinp    = (const float*)d_in[2];
    const float* norm1_w = (const float*)d_in[3];
    const float* norm2_w = (const float*)d_in[4];
    const float* attn_w  = (const float*)d_in[5];
    const float* proj_w  = (const float*)d_in[6];
    const float* scale_w = (const float*)d_in[7];
    const float* scale_b = (const float*)d_in[8];
    const float* gate_w  = (const float*)d_in[9];
    const float* up_w    = (const float*)d_in[10];
    const float* down_w  = (const float*)d_in[11];
    float* out = (float*)d_out;

    float *n1, *qkv, *scaleS, *scale_t, *q, *k, *vT, *S, *y, *x2, *n2, *gate, *up, *act;
    cudaGetSymbolAddress((void**)&n1, g_n1);
    cudaGetSymbolAddress((void**)&qkv, g_qkv);
    cudaGetSymbolAddress((void**)&scaleS, g_scaleS);
    cudaGetSymbolAddress((void**)&scale_t, g_scale_t);
    cudaGetSymbolAddress((void**)&q, g_q);
    cudaGetSymbolAddress((void**)&k, g_k);
    cudaGetSymbolAddress((void**)&vT, g_vT);
    cudaGetSymbolAddress((void**)&S, g_S);
    cudaGetSymbolAddress((void**)&y, g_y);
    cudaGetSymbolAddress((void**)&x2, g_x2);
    cudaGetSymbolAddress((void**)&n2, g_n2);
    cudaGetSymbolAddress((void**)&gate, g_gate);
    cudaGetSymbolAddress((void**)&up, g_up);
    cudaGetSymbolAddress((void**)&act, g_act);

    rmsnorm_kernel<<<T_SEQ, 256>>>(x, norm1_w, n1);

    gemm_bf3<<<dim3(QKV_N / BN, T_SEQ / BM, 1), 256>>>(
        n1, attn_w, nullptr, qkv, C_EMB, C_EMB, C_EMB, QKV_N, 0, 0, 0, 1);

    gemm_bf3<<<dim3(C_EMB / BN, T_SEQ / BM, 1), 256>>>(
        n1, scale_w, nullptr, scaleS, C_EMB, C_EMB, C_EMB, C_EMB, 0, 0, 0, 1);

    scale_reduce_kernel<<<NH * T_SEQ, 128>>>(scaleS, scale_b, scale_t);

    qkv_rope_split_kernel<<<(T_SEQ * QKV_N + 255) / 256, 256>>>(qkv, cosp, sinp, q, k, vT);

    gemm_bf3<<<dim3(T_SEQ / BN, T_SEQ / BM, NH), 256>>>(
        q, k, nullptr, S, HS, HS, HS, T_SEQ,
        (long long)T_SEQ * HS, (long long)T_SEQ * HS, (long long)T_SEQ * T_SEQ, 4);

    softmax_kernel<<<NH * T_SEQ, 256>>>(S, scale_t);

    gemm_bf3<<<dim3(HS / BN, T_SEQ / BM, NH), 256>>>(
        S, vT, nullptr, y, T_SEQ, T_SEQ, T_SEQ, C_EMB,
        (long long)T_SEQ * T_SEQ, (long long)HS * T_SEQ, (long long)HS, 4);

    gemm_bf3<<<dim3(C_EMB / BN, T_SEQ / BM, 1), 256>>>(
        y, proj_w, x, x2, C_EMB, C_EMB, C_EMB, C_EMB, 0, 0, 0, 1);

    rmsnorm_kernel<<<T_SEQ, 256>>>(x2, norm2_w, n2);

    gemm_bf3<<<dim3(FFN_N / BN, T_SEQ / BM, 1), 256>>>(
        n2, gate_w, nullptr, gate, C_EMB, C_EMB, C_EMB, FFN_N, 0, 0, 0, 1);

    gemm_bf3<<<dim3(FFN_N / BN, T_SEQ / BM, 1), 256>>>(
        n2, up_w, nullptr, up, C_EMB, C_EMB, C_EMB, FFN_N, 0, 0, 0, 1);

    silu_mul_kernel<<<(T_SEQ * FFN_N + 255) / 256, 256>>>(gate, up, act, T_SEQ * FFN_N);

    gemm_bf3<<<dim3(C_EMB / BN, T_SEQ / BM, 1), 256>>>(
        act, down_w, x2, out, FFN_N, FFN_N, FFN_N, C_EMB, 0, 0, 0, 1);
}

// round 12
// speedup vs baseline: 2.1523x; 1.4977x over previous
#include <cuda_runtime.h>
#include <math.h>
#include <stdint.h>

#define T_SEQ 2048
#define C_EMB 4096
#define NH    32
#define NG    8
#define HS    128
#define QKV_N 6144
#define FFN_N 11008
#define EPS   1e-5f
#define SF    0.08838834764831845f

static __device__ float g_n1     [T_SEQ * C_EMB];
static __device__ float g_qkv    [T_SEQ * QKV_N];
static __device__ float g_scaleS [T_SEQ * C_EMB];
static __device__ float g_scale_t[NH * T_SEQ];
static __device__ float g_q      [NH * T_SEQ * HS];
static __device__ float g_k      [NG * T_SEQ * HS];
static __device__ float g_vT     [NG * HS * T_SEQ];
static __device__ float g_S      [(size_t)NH * T_SEQ * T_SEQ];
static __device__ float g_y      [T_SEQ * C_EMB];
static __device__ float g_x2     [T_SEQ * C_EMB];
static __device__ float g_n2     [T_SEQ * C_EMB];
static __device__ float g_gate   [T_SEQ * FFN_N];
static __device__ float g_up     [T_SEQ * FFN_N];
static __device__ float g_act    [T_SEQ * FFN_N];

__device__ __forceinline__ float warpReduceSum(float v) {
    #pragma unroll
    for (int o = 16; o > 0; o >>= 1) v += __shfl_xor_sync(0xffffffffu, v, o);
    return v;
}
__device__ __forceinline__ float warpReduceMax(float v) {
    #pragma unroll
    for (int o = 16; o > 0; o >>= 1) v = fmaxf(v, __shfl_xor_sync(0xffffffffu, v, o));
    return v;
}

// ---------------------------------------------------------------------------
// rmsnorm
// ---------------------------------------------------------------------------
__global__ void rmsnorm_kernel(const float* __restrict__ x,
                               const float* __restrict__ w,
                               float* __restrict__ out) {
    int row = blockIdx.x;
    const float* xr = x + (size_t)row * C_EMB;
    float* orow = out + (size_t)row * C_EMB;
    int tid = threadIdx.x;
    float ss = 0.f;
    for (int i = tid; i < C_EMB; i += 256) { float v = xr[i]; ss += v * v; }
    __shared__ float sm[8];
    __shared__ float s_inv;
    float ws = warpReduceSum(ss);
    if ((tid & 31) == 0) sm[tid >> 5] = ws;
    __syncthreads();
    if (tid == 0) {
        float tot = 0.f;
        #pragma unroll
        for (int i = 0; i < 8; i++) tot += sm[i];
        s_inv = rsqrtf(tot / (float)C_EMB + EPS);
    }
    __syncthreads();
    float inv = s_inv;
    for (int i = tid; i < C_EMB; i += 256) orow[i] = xr[i] * inv * w[i];
}

// ---------------------------------------------------------------------------
// 3xBF16 split GEMM, templated N-tile (128 or 64).
// C[m][n] = sum_k A[m][k]*B[n][k] (+res).  Optional second output: tiles with
// bn >= N1 switch to (B2, C2, ldc2) with bn -= N1 (fuses two same-A GEMMs
// into one launch to kill wave-quantization tails).
// ---------------------------------------------------------------------------
#define BM 128
#define BK 16
#define PITCH 24   // uint16 elems per smem row: 48B, conflict-free (12r+q mod 32)

__device__ __forceinline__ void split2(float x0, float x1, uint32_t& h, uint32_t& l) {
    asm("cvt.rn.bf16x2.f32 %0, %1, %2;" : "=r"(h) : "f"(x1), "f"(x0));
    float f0 = __uint_as_float(h << 16);
    float f1 = __uint_as_float(h & 0xffff0000u);
    asm("cvt.rn.bf16x2.f32 %0, %1, %2;" : "=r"(l) : "f"(x1 - f1), "f"(x0 - f0));
}
__device__ __forceinline__ void store_split(uint16_t* hrow, uint16_t* lrow, float4 v) {
    uint32_t h0, l0, h1, l1;
    split2(v.x, v.y, h0, l0);
    split2(v.z, v.w, h1, l1);
    *(uint64_t*)hrow = ((uint64_t)h1 << 32) | h0;
    *(uint64_t*)lrow = ((uint64_t)l1 << 32) | l0;
}
__device__ __forceinline__ void mma_bf16(float* c, const uint32_t* a, const uint32_t* b) {
    asm volatile(
        "mma.sync.aligned.m16n8k16.row.col.f32.bf16.bf16.f32 "
        "{%0,%1,%2,%3}, {%4,%5,%6,%7}, {%8,%9}, {%0,%1,%2,%3};\n"
        : "+f"(c[0]), "+f"(c[1]), "+f"(c[2]), "+f"(c[3])
        : "r"(a[0]), "r"(a[1]), "r"(a[2]), "r"(a[3]), "r"(b[0]), "r"(b[1]));
}

template <int BNT>
__global__ __launch_bounds__(256, 1)
void gemm_bf3(const float* __restrict__ A,
              const float* __restrict__ B,
              const float* __restrict__ B2,
              const float* __restrict__ Dres,
              float* __restrict__ C,
              float* __restrict__ C2,
              int N1, int K, int lda, int ldb, int ldc, int ldc2,
              long long sA, long long sB, long long sC, int bdiv) {
    constexpr int NJ = BNT / 16;        // b-fragments per warp (8 or 4)
    constexpr int BJ = BNT / 64;        // B fill iterations (2 or 1)
    // 0=h 1=l
    __shared__ __align__(16) uint16_t smA[2][2][BM][PITCH];
    __shared__ __align__(16) uint16_t smB[2][2][BNT][PITCH];

    int bn = blockIdx.x * BNT;
    if (N1 > 0 && bn >= N1) { B = B2; C = C2; ldc = ldc2; bn -= N1; }

    int z = blockIdx.z;
    A += (long long)z * sA;
    B += (long long)(z / bdiv) * sB;
    C += (long long)z * sC;
    if (Dres) Dres += (long long)z * sC;

    const int bm = blockIdx.y * BM;
    const int tid  = threadIdx.x;
    const int lane = tid & 31;
    const int warp = tid >> 5;
    const int wm = (warp & 3) * 32;
    const int wn = (warp >> 2) * (BNT / 2);
    const int grp = lane >> 2;   // 0..7
    const int qid = lane & 3;    // 0..3

    // fill mapping: float4 index f = tid + 256*j -> row f>>2, elem col (f&3)*4
    const int frow = tid >> 2;          // 0..63 (j adds 64)
    const int fkq  = (tid & 3) * 4;

    const float* AgP[2];
    AgP[0] = A + (size_t)(bm + frow) * lda + fkq;
    AgP[1] = A + (size_t)(bm + frow + 64) * lda + fkq;
    const float* BgP[2];
    BgP[0] = B + (size_t)(bn + frow) * ldb + fkq;
    BgP[1] = (BJ == 2) ? (B + (size_t)(bn + frow + 64) * ldb + fkq) : BgP[0];

    float acc[2][NJ][4];
    #pragma unroll
    for (int mi = 0; mi < 2; mi++)
        #pragma unroll
        for (int nj = 0; nj < NJ; nj++)
            #pragma unroll
            for (int q = 0; q < 4; q++) acc[mi][nj][q] = 0.f;

    const int nk = K / BK;

    // preload + store chunk 0
    {
        #pragma unroll
        for (int j = 0; j < 2; j++) {
            float4 v = *(const float4*)(AgP[j]);
            store_split(&smA[0][0][frow + 64 * j][fkq], &smA[0][1][frow + 64 * j][fkq], v);
        }
        #pragma unroll
        for (int j = 0; j < BJ; j++) {
            float4 v = *(const float4*)(BgP[j]);
            store_split(&smB[0][0][frow + 64 * j][fkq], &smB[0][1][frow + 64 * j][fkq], v);
        }
    }
    __syncthreads();

    for (int kt = 0; kt < nk; kt++) {
        const int cur = kt & 1;
        const int nxt = cur ^ 1;
        const bool has_next = (kt + 1 < nk);

        float4 pa[2], pb[BJ];
        if (has_next) {
            const int ko = (kt + 1) * BK;
            #pragma unroll
            for (int j = 0; j < 2; j++) pa[j] = *(const float4*)(AgP[j] + ko);
            #pragma unroll
            for (int j = 0; j < BJ; j++) pb[j] = *(const float4*)(BgP[j] + ko);
        }

        // fragment loads (scalar LDS.32, conflict-free)
        uint32_t ah[2][4], al[2][4], bh[NJ][2], bl[NJ][2];
        #pragma unroll
        for (int mi = 0; mi < 2; mi++) {
            int m0 = wm + mi * 16 + grp;
            int m1 = m0 + 8;
            int k0 = 2 * qid, k1 = 8 + 2 * qid;
            ah[mi][0] = *(const uint32_t*)&smA[cur][0][m0][k0];
            ah[mi][1] = *(const uint32_t*)&smA[cur][0][m1][k0];
            ah[mi][2] = *(const uint32_t*)&smA[cur][0][m0][k1];
            ah[mi][3] = *(const uint32_t*)&smA[cur][0][m1][k1];
            al[mi][0] = *(const uint32_t*)&smA[cur][1][m0][k0];
            al[mi][1] = *(const uint32_t*)&smA[cur][1][m1][k0];
            al[mi][2] = *(const uint32_t*)&smA[cur][1][m0][k1];
            al[mi][3] = *(const uint32_t*)&smA[cur][1][m1][k1];
        }
        #pragma unroll
        for (int nj = 0; nj < NJ; nj++) {
            int n = wn + nj * 8 + grp;
            int k0 = 2 * qid, k1 = 8 + 2 * qid;
            bh[nj][0] = *(const uint32_t*)&smB[cur][0][n][k0];
            bh[nj][1] = *(const uint32_t*)&smB[cur][0][n][k1];
            bl[nj][0] = *(const uint32_t*)&smB[cur][1][n][k0];
            bl[nj][1] = *(const uint32_t*)&smB[cur][1][n][k1];
        }

        #pragma unroll
        for (int mi = 0; mi < 2; mi++)
            #pragma unroll
            for (int nj = 0; nj < NJ; nj++)
                mma_bf16(acc[mi][nj], ah[mi], bh[nj]);
        #pragma unroll
        for (int mi = 0; mi < 2; mi++)
            #pragma unroll
            for (int nj = 0; nj < NJ; nj++)
                mma_bf16(acc[mi][nj], al[mi], bh[nj]);
        #pragma unroll
        for (int mi = 0; mi < 2; mi++)
            #pragma unroll
            for (int nj = 0; nj < NJ; nj++)
                mma_bf16(acc[mi][nj], ah[mi], bl[nj]);

        if (has_next) {
            #pragma unroll
            for (int j = 0; j < 2; j++)
                store_split(&smA[nxt][0][frow + 64 * j][fkq], &smA[nxt][1][frow + 64 * j][fkq], pa[j]);
            #pragma unroll
            for (int j = 0; j < BJ; j++)
                store_split(&smB[nxt][0][frow + 64 * j][fkq], &smB[nxt][1][frow + 64 * j][fkq], pb[j]);
        }
        __syncthreads();
    }

    #pragma unroll
    for (int mi = 0; mi < 2; mi++) {
        #pragma unroll
        for (int nj = 0; nj < NJ; nj++) {
            int row = bm + wm + mi * 16 + grp;
            int col = bn + wn + nj * 8 + qid * 2;
            size_t i0 = (size_t)row * ldc + col;
            size_t i1 = (size_t)(row + 8) * ldc + col;
            float v0 = acc[mi][nj][0], v1 = acc[mi][nj][1];
            float v2 = acc[mi][nj][2], v3 = acc[mi][nj][3];
            if (Dres) {
                v0 += Dres[i0]; v1 += Dres[i0 + 1];
                v2 += Dres[i1]; v3 += Dres[i1 + 1];
            }
            C[i0] = v0; C[i0 + 1] = v1;
            C[i1] = v2; C[i1 + 1] = v3;
        }
    }
}

// ---------------------------------------------------------------------------
// qkv split + rope (v transposed)
// ---------------------------------------------------------------------------
__global__ void qkv_rope_split_kernel(const float* __restrict__ qkv,
                                      const float* __restrict__ cos_,
                                      const float* __restrict__ sin_,
                                      float* __restrict__ q,
                                      float* __restrict__ k,
                                      float* __restrict__ vT) {
    int idx = blockIdx.x * 256 + threadIdx.x;
    if (idx >= T_SEQ * QKV_N) return;
    int t = idx / QKV_N;
    int c = idx - t * QKV_N;
    int g = c / (6 * HS);
    int rem = c - g * 6 * HS;
    int slot = rem / HS;
    int d = rem - slot * HS;
    float val = qkv[idx];
    if (slot < 5) {
        int hb = idx - d;
        float partner = (d < 64) ? -qkv[hb + d + 64] : qkv[hb + d - 64];
        val = val * cos_[t * HS + d] + partner * sin_[t * HS + d];
    }
    if (slot < 4)       q[((size_t)(g * 4 + slot) * T_SEQ + t) * HS + d] = val;
    else if (slot == 4) k[((size_t)g * T_SEQ + t) * HS + d] = val;
    else                vT[((size_t)g * HS + d) * T_SEQ + t] = val;
}

__global__ void scale_reduce_kernel(const float* __restrict__ S,
                                    const float* __restrict__ bias,
                                    float* __restrict__ scale_t) {
    int b = blockIdx.x;
    int h = b / T_SEQ;
    int t = b - h * T_SEQ;
    int d = threadIdx.x;
    int c = h * HS + d;
    float vv = fmaxf(S[(size_t)t * C_EMB + c] + bias[c], 0.f);
    __shared__ float sm[4];
    float ws = warpReduceSum(vv);
    if ((d & 31) == 0) sm[d >> 5] = ws;
    __syncthreads();
    if (d == 0) scale_t[b] = SF * ((sm[0] + sm[1] + sm[2] + sm[3]) / (float)HS);
}

__global__ void softmax_kernel(float* __restrict__ S,
                               const float* __restrict__ scale_t) {
    size_t r = blockIdx.x;
    float alpha = scale_t[r];
    float* row = S + r * (size_t)T_SEQ;
    int tid = threadIdx.x;
    float vals[8];
    float m = -INFINITY;
    #pragma unroll
    for (int i = 0; i < 8; i++) {
        vals[i] = alpha * row[tid + 256 * i];
        m = fmaxf(m, vals[i]);
    }
    __shared__ float sm[8];
    __shared__ float s_b;
    float wm = warpReduceMax(m);
    if ((tid & 31) == 0) sm[tid >> 5] = wm;
    __syncthreads();
    if (tid == 0) {
        float mm = sm[0];
        #pragma unroll
        for (int i = 1; i < 8; i++) mm = fmaxf(mm, sm[i]);
        s_b = mm;
    }
    __syncthreads();
    m = s_b;
    float s = 0.f;
    #pragma unroll
    for (int i = 0; i < 8; i++) { vals[i] = __expf(vals[i] - m); s += vals[i]; }
    __syncthreads();
    float ws = warpReduceSum(s);
    if ((tid & 31) == 0) sm[tid >> 5] = ws;
    __syncthreads();
    if (tid == 0) {
        float tot = 0.f;
        #pragma unroll
        for (int i = 0; i < 8; i++) tot += sm[i];
        s_b = 1.f / tot;
    }
    __syncthreads();
    float inv = s_b;
    #pragma unroll
    for (int i = 0; i < 8; i++) row[tid + 256 * i] = vals[i] * inv;
}

__global__ void silu_mul_kernel(const float* __restrict__ g,
                                const float* __restrict__ u,
                                float* __restrict__ out, int n) {
    int idx = blockIdx.x * 256 + threadIdx.x;
    if (idx >= n) return;
    float x = g[idx];
    out[idx] = x / (1.f + __expf(-x)) * u[idx];
}

// ---------------------------------------------------------------------------
extern "C" void kernel_launch(void* const* d_in, const int* in_sizes, int n_in,
                              void* d_out, int out_size) {
    const float* x       = (const float*)d_in[0];
    const float* cosp    = (const float*)d_in[1];
    const float* sinp    = (const float*)d_in[2];
    const float* norm1_w = (const float*)d_in[3];
    const float* norm2_w = (const float*)d_in[4];
    const float* attn_w  = (const float*)d_in[5];
    const float* proj_w  = (const float*)d_in[6];
    const float* scale_w = (const float*)d_in[7];
    const float* scale_b = (const float*)d_in[8];
    const float* gate_w  = (const float*)d_in[9];
    const float* up_w    = (const float*)d_in[10];
    const float* down_w  = (const float*)d_in[11];
    float* out = (float*)d_out;

    float *n1, *qkv, *scaleS, *scale_t, *q, *k, *vT, *S, *y, *x2, *n2, *gate, *up, *act;
    cudaGetSymbolAddress((void**)&n1, g_n1);
    cudaGetSymbolAddress((void**)&qkv, g_qkv);
    cudaGetSymbolAddress((void**)&scaleS, g_scaleS);
    cudaGetSymbolAddress((void**)&scale_t, g_scale_t);
    cudaGetSymbolAddress((void**)&q, g_q);
    cudaGetSymbolAddress((void**)&k, g_k);
    cudaGetSymbolAddress((void**)&vT, g_vT);
    cudaGetSymbolAddress((void**)&S, g_S);
    cudaGetSymbolAddress((void**)&y, g_y);
    cudaGetSymbolAddress((void**)&x2, g_x2);
    cudaGetSymbolAddress((void**)&n2, g_n2);
    cudaGetSymbolAddress((void**)&gate, g_gate);
    cudaGetSymbolAddress((void**)&up, g_up);
    cudaGetSymbolAddress((void**)&act, g_act);

    rmsnorm_kernel<<<T_SEQ, 256>>>(x, norm1_w, n1);

    // fused qkv | scaleS  (both read n1; switch at bn >= 6144)
    gemm_bf3<128><<<dim3((QKV_N + C_EMB) / 128, T_SEQ / BM, 1), 256>>>(
        n1, attn_w, scale_w, nullptr, qkv, scaleS,
        QKV_N, C_EMB, C_EMB, C_EMB, QKV_N, C_EMB, 0, 0, 0, 1);

    scale_reduce_kernel<<<NH * T_SEQ, 128>>>(scaleS, scale_b, scale_t);

    qkv_rope_split_kernel<<<(T_SEQ * QKV_N + 255) / 256, 256>>>(qkv, cosp, sinp, q, k, vT);

    // scores
    gemm_bf3<128><<<dim3(T_SEQ / 128, T_SEQ / BM, NH), 256>>>(
        q, k, nullptr, nullptr, S, nullptr,
        0, HS, HS, HS, T_SEQ, 0,
        (long long)T_SEQ * HS, (long long)T_SEQ * HS, (long long)T_SEQ * T_SEQ, 4);

    softmax_kernel<<<NH * T_SEQ, 256>>>(S, scale_t);

    // AV (BN=64 for tail reduction)
    gemm_bf3<64><<<dim3(HS / 64, T_SEQ / BM, NH), 256>>>(
        S, vT, nullptr, nullptr, y, nullptr,
        0, T_SEQ, T_SEQ, T_SEQ, C_EMB, 0,
        (long long)T_SEQ * T_SEQ, (long long)HS * T_SEQ, (long long)HS, 4);

    // proj + residual (BN=64)
    gemm_bf3<64><<<dim3(C_EMB / 64, T_SEQ / BM, 1), 256>>>(
        y, proj_w, nullptr, x, x2, nullptr,
        0, C_EMB, C_EMB, C_EMB, C_EMB, 0, 0, 0, 0, 1);

    rmsnorm_kernel<<<T_SEQ, 256>>>(x2, norm2_w, n2);

    // fused gate | up  (both read n2; switch at bn >= 11008)
    gemm_bf3<128><<<dim3(2 * FFN_N / 128, T_SEQ / BM, 1), 256>>>(
        n2, gate_w, up_w, nullptr, gate, up,
        FFN_N, C_EMB, C_EMB, C_EMB, FFN_N, FFN_N, 0, 0, 0, 1);

    silu_mul_kernel<<<(T_SEQ * FFN_N + 255) / 256, 256>>>(gate, up, act, T_SEQ * FFN_N);

    // down + residual (BN=64)
    gemm_bf3<64><<<dim3(C_EMB / 64, T_SEQ / BM, 1), 256>>>(
        act, down_w, nullptr, x2, out,  nullptr,
        0, FFN_N, FFN_N, FFN_N, C_EMB, 0, 0, 0, 0, 1);
}

// round 13
// speedup vs baseline: 2.3497x; 1.0917x over previous
#include <cuda_runtime.h>
#include <math.h>
#include <stdint.h>

#define T_SEQ 2048
#define C_EMB 4096
#define NH    32
#define NG    8
#define HS    128
#define QKV_N 6144
#define FFN_N 11008
#define EPS   1e-5f
#define SF    0.08838834764831845f

static __device__ float g_n1     [T_SEQ * C_EMB];
static __device__ float g_qkv    [T_SEQ * QKV_N];
static __device__ float g_scaleS [T_SEQ * C_EMB];
static __device__ float g_scale_t[NH * T_SEQ];
static __device__ float g_q      [NH * T_SEQ * HS];
static __device__ float g_k      [NG * T_SEQ * HS];
static __device__ float g_vT     [NG * HS * T_SEQ];
static __device__ float g_S      [(size_t)NH * T_SEQ * T_SEQ];
static __device__ float g_y      [T_SEQ * C_EMB];
static __device__ float g_x2     [T_SEQ * C_EMB];
static __device__ float g_n2     [T_SEQ * C_EMB];
static __device__ float g_gate   [T_SEQ * FFN_N];
static __device__ float g_up     [T_SEQ * FFN_N];
static __device__ float g_act    [T_SEQ * FFN_N];

__device__ __forceinline__ float warpReduceSum(float v) {
    #pragma unroll
    for (int o = 16; o > 0; o >>= 1) v += __shfl_xor_sync(0xffffffffu, v, o);
    return v;
}
__device__ __forceinline__ float warpReduceMax(float v) {
    #pragma unroll
    for (int o = 16; o > 0; o >>= 1) v = fmaxf(v, __shfl_xor_sync(0xffffffffu, v, o));
    return v;
}

// ---------------------------------------------------------------------------
// rmsnorm
// ---------------------------------------------------------------------------
__global__ void rmsnorm_kernel(const float* __restrict__ x,
                               const float* __restrict__ w,
                               float* __restrict__ out) {
    int row = blockIdx.x;
    const float* xr = x + (size_t)row * C_EMB;
    float* orow = out + (size_t)row * C_EMB;
    int tid = threadIdx.x;
    float ss = 0.f;
    for (int i = tid; i < C_EMB; i += 256) { float v = xr[i]; ss += v * v; }
    __shared__ float sm[8];
    __shared__ float s_inv;
    float ws = warpReduceSum(ss);
    if ((tid & 31) == 0) sm[tid >> 5] = ws;
    __syncthreads();
    if (tid == 0) {
        float tot = 0.f;
        #pragma unroll
        for (int i = 0; i < 8; i++) tot += sm[i];
        s_inv = rsqrtf(tot / (float)C_EMB + EPS);
    }
    __syncthreads();
    float inv = s_inv;
    for (int i = tid; i < C_EMB; i += 256) orow[i] = xr[i] * inv * w[i];
}

// ---------------------------------------------------------------------------
// 3xBF16 split GEMM, templated N-tile (128 or 64), depth-2 LDG pipeline.
// C[m][n] = sum_k A[m][k]*B[n][k] (+res).  Tiles with bn >= N1 switch to
// (B2, C2, ldc2) with bn -= N1 (fuses two same-A GEMMs into one launch).
// ---------------------------------------------------------------------------
#define BM 128
#define BK 16
#define PITCH 24   // uint16 elems per smem row: 48B, conflict-free (12r+q mod 32)

__device__ __forceinline__ void split2(float x0, float x1, uint32_t& h, uint32_t& l) {
    asm("cvt.rn.bf16x2.f32 %0, %1, %2;" : "=r"(h) : "f"(x1), "f"(x0));
    float f0 = __uint_as_float(h << 16);
    float f1 = __uint_as_float(h & 0xffff0000u);
    asm("cvt.rn.bf16x2.f32 %0, %1, %2;" : "=r"(l) : "f"(x1 - f1), "f"(x0 - f0));
}
__device__ __forceinline__ void store_split(uint16_t* hrow, uint16_t* lrow, float4 v) {
    uint32_t h0, l0, h1, l1;
    split2(v.x, v.y, h0, l0);
    split2(v.z, v.w, h1, l1);
    *(uint64_t*)hrow = ((uint64_t)h1 << 32) | h0;
    *(uint64_t*)lrow = ((uint64_t)l1 << 32) | l0;
}
__device__ __forceinline__ void mma_bf16(float* c, const uint32_t* a, const uint32_t* b) {
    asm volatile(
        "mma.sync.aligned.m16n8k16.row.col.f32.bf16.bf16.f32 "
        "{%0,%1,%2,%3}, {%4,%5,%6,%7}, {%8,%9}, {%0,%1,%2,%3};\n"
        : "+f"(c[0]), "+f"(c[1]), "+f"(c[2]), "+f"(c[3])
        : "r"(a[0]), "r"(a[1]), "r"(a[2]), "r"(a[3]), "r"(b[0]), "r"(b[1]));
}

template <int BNT>
__global__ __launch_bounds__(256, 1)
void gemm_bf3(const float* __restrict__ A,
              const float* __restrict__ B,
              const float* __restrict__ B2,
              const float* __restrict__ Dres,
              float* __restrict__ C,
              float* __restrict__ C2,
              int N1, int K, int lda, int ldb, int ldc, int ldc2,
              long long sA, long long sB, long long sC, int bdiv) {
    constexpr int NJ = BNT / 16;        // b-fragments per warp (8 or 4)
    constexpr int BJ = BNT / 64;        // B fill iterations (2 or 1)
    __shared__ __align__(16) uint16_t smA[2][2][BM][PITCH];
    __shared__ __align__(16) uint16_t smB[2][2][BNT][PITCH];

    int bn = blockIdx.x * BNT;
    if (N1 > 0 && bn >= N1) { B = B2; C = C2; ldc = ldc2; bn -= N1; }

    int z = blockIdx.z;
    A += (long long)z * sA;
    B += (long long)(z / bdiv) * sB;
    C += (long long)z * sC;
    if (Dres) Dres += (long long)z * sC;

    const int bm = blockIdx.y * BM;
    const int tid  = threadIdx.x;
    const int lane = tid & 31;
    const int warp = tid >> 5;
    const int wm = (warp & 3) * 32;
    const int wn = (warp >> 2) * (BNT / 2);
    const int grp = lane >> 2;   // 0..7
    const int qid = lane & 3;    // 0..3

    const int frow = tid >> 2;          // 0..63 (j adds 64)
    const int fkq  = (tid & 3) * 4;

    const float* AgP[2];
    AgP[0] = A + (size_t)(bm + frow) * lda + fkq;
    AgP[1] = A + (size_t)(bm + frow + 64) * lda + fkq;
    const float* BgP[2];
    BgP[0] = B + (size_t)(bn + frow) * ldb + fkq;
    BgP[1] = (BJ == 2) ? (B + (size_t)(bn + frow + 64) * ldb + fkq) : BgP[0];

    float acc[2][NJ][4];
    #pragma unroll
    for (int mi = 0; mi < 2; mi++)
        #pragma unroll
        for (int nj = 0; nj < NJ; nj++)
            #pragma unroll
            for (int q = 0; q < 4; q++) acc[mi][nj][q] = 0.f;

    const int nk = K / BK;

    // chunk 0 -> smem buf0 directly
    {
        #pragma unroll
        for (int j = 0; j < 2; j++) {
            float4 v = *(const float4*)(AgP[j]);
            store_split(&smA[0][0][frow + 64 * j][fkq], &smA[0][1][frow + 64 * j][fkq], v);
        }
        #pragma unroll
        for (int j = 0; j < BJ; j++) {
            float4 v = *(const float4*)(BgP[j]);
            store_split(&smB[0][0][frow + 64 * j][fkq], &smB[0][1][frow + 64 * j][fkq], v);
        }
    }
    // chunk 1 -> registers L1
    float4 L1a[2], L1b[BJ];
    if (nk > 1) {
        #pragma unroll
        for (int j = 0; j < 2; j++) L1a[j] = *(const float4*)(AgP[j] + BK);
        #pragma unroll
        for (int j = 0; j < BJ; j++) L1b[j] = *(const float4*)(BgP[j] + BK);
    }
    __syncthreads();

    for (int kt = 0; kt < nk; kt++) {
        const int cur = kt & 1;
        const int nxt = cur ^ 1;

        // issue loads for chunk kt+2 (two chunks ahead)
        float4 L2a[2], L2b[BJ];
        if (kt + 2 < nk) {
            const int ko = (kt + 2) * BK;
            #pragma unroll
            for (int j = 0; j < 2; j++) L2a[j] = *(const float4*)(AgP[j] + ko);
            #pragma unroll
            for (int j = 0; j < BJ; j++) L2b[j] = *(const float4*)(BgP[j] + ko);
        }

        // fragment loads (scalar LDS.32, conflict-free)
        uint32_t ah[2][4], al[2][4], bh[NJ][2], bl[NJ][2];
        #pragma unroll
        for (int mi = 0; mi < 2; mi++) {
            int m0 = wm + mi * 16 + grp;
            int m1 = m0 + 8;
            int k0 = 2 * qid, k1 = 8 + 2 * qid;
            ah[mi][0] = *(const uint32_t*)&smA[cur][0][m0][k0];
            ah[mi][1] = *(const uint32_t*)&smA[cur][0][m1][k0];
            ah[mi][2] = *(const uint32_t*)&smA[cur][0][m0][k1];
            ah[mi][3] = *(const uint32_t*)&smA[cur][0][m1][k1];
            al[mi][0] = *(const uint32_t*)&smA[cur][1][m0][k0];
            al[mi][1] = *(const uint32_t*)&smA[cur][1][m1][k0];
            al[mi][2] = *(const uint32_t*)&smA[cur][1][m0][k1];
            al[mi][3] = *(const uint32_t*)&smA[cur][1][m1][k1];
        }
        #pragma unroll
        for (int nj = 0; nj < NJ; nj++) {
            int n = wn + nj * 8 + grp;
            int k0 = 2 * qid, k1 = 8 + 2 * qid;
            bh[nj][0] = *(const uint32_t*)&smB[cur][0][n][k0];
            bh[nj][1] = *(const uint32_t*)&smB[cur][0][n][k1];
            bl[nj][0] = *(const uint32_t*)&smB[cur][1][n][k0];
            bl[nj][1] = *(const uint32_t*)&smB[cur][1][n][k1];
        }

        #pragma unroll
        for (int mi = 0; mi < 2; mi++)
            #pragma unroll
            for (int nj = 0; nj < NJ; nj++)
                mma_bf16(acc[mi][nj], ah[mi], bh[nj]);
        #pragma unroll
        for (int mi = 0; mi < 2; mi++)
            #pragma unroll
            for (int nj = 0; nj < NJ; nj++)
                mma_bf16(acc[mi][nj], al[mi], bh[nj]);
        #pragma unroll
        for (int mi = 0; mi < 2; mi++)
            #pragma unroll
            for (int nj = 0; nj < NJ; nj++)
                mma_bf16(acc[mi][nj], ah[mi], bl[nj]);

        // store chunk kt+1 (in L1) into the other buffer, then rotate regs
        if (kt + 1 < nk) {
            #pragma unroll
            for (int j = 0; j < 2; j++)
                store_split(&smA[nxt][0][frow + 64 * j][fkq], &smA[nxt][1][frow + 64 * j][fkq], L1a[j]);
            #pragma unroll
            for (int j = 0; j < BJ; j++)
                store_split(&smB[nxt][0][frow + 64 * j][fkq], &smB[nxt][1][frow + 64 * j][fkq], L1b[j]);
        }
        if (kt + 2 < nk) {
            #pragma unroll
            for (int j = 0; j < 2; j++) L1a[j] = L2a[j];
            #pragma unroll
            for (int j = 0; j < BJ; j++) L1b[j] = L2b[j];
        }
        __syncthreads();
    }

    #pragma unroll
    for (int mi = 0; mi < 2; mi++) {
        #pragma unroll
        for (int nj = 0; nj < NJ; nj++) {
            int row = bm + wm + mi * 16 + grp;
            int col = bn + wn + nj * 8 + qid * 2;
            size_t i0 = (size_t)row * ldc + col;
            size_t i1 = (size_t)(row + 8) * ldc + col;
            float v0 = acc[mi][nj][0], v1 = acc[mi][nj][1];
            float v2 = acc[mi][nj][2], v3 = acc[mi][nj][3];
            if (Dres) {
                v0 += Dres[i0]; v1 += Dres[i0 + 1];
                v2 += Dres[i1]; v3 += Dres[i1 + 1];
            }
            C[i0] = v0; C[i0 + 1] = v1;
            C[i1] = v2; C[i1 + 1] = v3;
        }
    }
}

// ---------------------------------------------------------------------------
// qkv split + rope (v transposed)
// ---------------------------------------------------------------------------
__global__ void qkv_rope_split_kernel(const float* __restrict__ qkv,
                                      const float* __restrict__ cos_,
                                      const float* __restrict__ sin_,
                                      float* __restrict__ q,
                                      float* __restrict__ k,
                                      float* __restrict__ vT) {
    int idx = blockIdx.x * 256 + threadIdx.x;
    if (idx >= T_SEQ * QKV_N) return;
    int t = idx / QKV_N;
    int c = idx - t * QKV_N;
    int g = c / (6 * HS);
    int rem = c - g * 6 * HS;
    int slot = rem / HS;
    int d = rem - slot * HS;
    float val = qkv[idx];
    if (slot < 5) {
        int hb = idx - d;
        float partner = (d < 64) ? -qkv[hb + d + 64] : qkv[hb + d - 64];
        val = val * cos_[t * HS + d] + partner * sin_[t * HS + d];
    }
    if (slot < 4)       q[((size_t)(g * 4 + slot) * T_SEQ + t) * HS + d] = val;
    else if (slot == 4) k[((size_t)g * T_SEQ + t) * HS + d] = val;
    else                vT[((size_t)g * HS + d) * T_SEQ + t] = val;
}

__global__ void scale_reduce_kernel(const float* __restrict__ S,
                                    const float* __restrict__ bias,
                                    float* __restrict__ scale_t) {
    int b = blockIdx.x;
    int h = b / T_SEQ;
    int t = b - h * T_SEQ;
    int d = threadIdx.x;
    int c = h * HS + d;
    float vv = fmaxf(S[(size_t)t * C_EMB + c] + bias[c], 0.f);
    __shared__ float sm[4];
    float ws = warpReduceSum(vv);
    if ((d & 31) == 0) sm[d >> 5] = ws;
    __syncthreads();
    if (d == 0) scale_t[b] = SF * ((sm[0] + sm[1] + sm[2] + sm[3]) / (float)HS);
}

__global__ void softmax_kernel(float* __restrict__ S,
                               const float* __restrict__ scale_t) {
    size_t r = blockIdx.x;
    float alpha = scale_t[r];
    float* row = S + r * (size_t)T_SEQ;
    int tid = threadIdx.x;
    float vals[8];
    float m = -INFINITY;
    #pragma unroll
    for (int i = 0; i < 8; i++) {
        vals[i] = alpha * row[tid + 256 * i];
        m = fmaxf(m, vals[i]);
    }
    __shared__ float sm[8];
    __shared__ float s_b;
    float wm = warpReduceMax(m);
    if ((tid & 31) == 0) sm[tid >> 5] = wm;
    __syncthreads();
    if (tid == 0) {
        float mm = sm[0];
        #pragma unroll
        for (int i = 1; i < 8; i++) mm = fmaxf(mm, sm[i]);
        s_b = mm;
    }
    __syncthreads();
    m = s_b;
    float s = 0.f;
    #pragma unroll
    for (int i = 0; i < 8; i++) { vals[i] = __expf(vals[i] - m); s += vals[i]; }
    __syncthreads();
    float ws = warpReduceSum(s);
    if ((tid & 31) == 0) sm[tid >> 5] = ws;
    __syncthreads();
    if (tid == 0) {
        float tot = 0.f;
        #pragma unroll
        for (int i = 0; i < 8; i++) tot += sm[i];
        s_b = 1.f / tot;
    }
    __syncthreads();
    float inv = s_b;
    #pragma unroll
    for (int i = 0; i < 8; i++) row[tid + 256 * i] = vals[i] * inv;
}

__global__ void silu_mul_kernel(const float* __restrict__ g,
                                const float* __restrict__ u,
                                float* __restrict__ out, int n) {
    int idx = blockIdx.x * 256 + threadIdx.x;
    if (idx >= n) return;
    float x = g[idx];
    out[idx] = x / (1.f + __expf(-x)) * u[idx];
}

// ---------------------------------------------------------------------------
extern "C" void kernel_launch(void* const* d_in, const int* in_sizes, int n_in,
                              void* d_out, int out_size) {
    const float* x       = (const float*)d_in[0];
    const float* cosp    = (const float*)d_in[1];
    const float* sinp    = (const float*)d_in[2];
    const float* norm1_w = (const float*)d_in[3];
    const float* norm2_w = (const float*)d_in[4];
    const float* attn_w  = (const float*)d_in[5];
    const float* proj_w  = (const float*)d_in[6];
    const float* scale_w = (const float*)d_in[7];
    const float* scale_b = (const float*)d_in[8];
    const float* gate_w  = (const float*)d_in[9];
    const float* up_w    = (const float*)d_in[10];
    const float* down_w  = (const float*)d_in[11];
    float* out = (float*)d_out;

    float *n1, *qkv, *scaleS, *scale_t, *q, *k, *vT, *S, *y, *x2, *n2, *gate, *up, *act;
    cudaGetSymbolAddress((void**)&n1, g_n1);
    cudaGetSymbolAddress((void**)&qkv, g_qkv);
    cudaGetSymbolAddress((void**)&scaleS, g_scaleS);
    cudaGetSymbolAddress((void**)&scale_t, g_scale_t);
    cudaGetSymbolAddress((void**)&q, g_q);
    cudaGetSymbolAddress((void**)&k, g_k);
    cudaGetSymbolAddress((void**)&vT, g_vT);
    cudaGetSymbolAddress((void**)&S, g_S);
    cudaGetSymbolAddress((void**)&y, g_y);
    cudaGetSymbolAddress((void**)&x2, g_x2);
    cudaGetSymbolAddress((void**)&n2, g_n2);
    cudaGetSymbolAddress((void**)&gate, g_gate);
    cudaGetSymbolAddress((void**)&up, g_up);
    cudaGetSymbolAddress((void**)&act, g_act);

    rmsnorm_kernel<<<T_SEQ, 256>>>(x, norm1_w, n1);

    // fused qkv | scaleS
    gemm_bf3<128><<<dim3((QKV_N + C_EMB) / 128, T_SEQ / BM, 1), 256>>>(
        n1, attn_w, scale_w, nullptr, qkv, scaleS,
        QKV_N, C_EMB, C_EMB, C_EMB, QKV_N, C_EMB, 0, 0, 0, 1);

    scale_reduce_kernel<<<NH * T_SEQ, 128>>>(scaleS, scale_b, scale_t);

    qkv_rope_split_kernel<<<(T_SEQ * QKV_N + 255) / 256, 256>>>(qkv, cosp, sinp, q, k, vT);

    // scores
    gemm_bf3<128><<<dim3(T_SEQ / 128, T_SEQ / BM, NH), 256>>>(
        q, k, nullptr, nullptr, S, nullptr,
        0, HS, HS, HS, T_SEQ, 0,
        (long long)T_SEQ * HS, (long long)T_SEQ * HS, (long long)T_SEQ * T_SEQ, 4);

    softmax_kernel<<<NH * T_SEQ, 256>>>(S, scale_t);

    // AV (BN=64)
    gemm_bf3<64><<<dim3(HS / 64, T_SEQ / BM, NH), 256>>>(
        S, vT, nullptr, nullptr, y, nullptr,
        0, T_SEQ, T_SEQ, T_SEQ, C_EMB, 0,
        (long long)T_SEQ * T_SEQ, (long long)HS * T_SEQ, (long long)HS, 4);

    // proj + residual (BN=64)
    gemm_bf3<64><<<dim3(C_EMB / 64, T_SEQ / BM, 1), 256>>>(
        y, proj_w, nullptr, x, x2, nullptr,
        0, C_EMB, C_EMB, C_EMB, C_EMB, 0, 0, 0, 0, 1);

    rmsnorm_kernel<<<T_SEQ, 256>>>(x2, norm2_w, n2);

    // fused gate | up
    gemm_bf3<128><<<dim3(2 * FFN_N / 128, T_SEQ / BM, 1), 256>>>(
        n2, gate_w, up_w, nullptr, gate, up,
        FFN_N, C_EMB, C_EMB, C_EMB, FFN_N, FFN_N, 0, 0, 0, 1);

    silu_mul_kernel<<<(T_SEQ * FFN_N + 255) / 256, 256>>>(gate, up, act, T_SEQ * FFN_N);

    // down + residual (BN=64)
    gemm_bf3<64><<<dim3(C_EMB / 64, T_SEQ / BM, 1), 256>>>(
        act, down_w, nullptr, x2, out,  nullptr,
        0, FFN_N, FFN_N, FFN_N, C_EMB, 0, 0, 0, 0, 1);
}

// round 15
// speedup vs baseline: 2.6523x; 1.1288x over previous
#include <cuda_runtime.h>
#include <cuda_fp16.h>
#include <math.h>
#include <stdint.h>

#define T_SEQ 2048
#define C_EMB 4096
#define NH    32
#define NG    8
#define HS    128
#define QKV_N 6144
#define FFN_N 11008
#define EPS   1e-5f
#define SF    0.08838834764831845f

static __device__ float g_n1     [T_SEQ * C_EMB];
static __device__ float g_qkv    [T_SEQ * QKV_N];
static __device__ float g_scaleS [T_SEQ * C_EMB];
static __device__ float g_scale_t[NH * T_SEQ];
static __device__ float g_q      [NH * T_SEQ * HS];
static __device__ float g_k      [NG * T_SEQ * HS];
static __device__ float g_vT     [NG * HS * T_SEQ];
static __device__ float g_S      [(size_t)NH * T_SEQ * T_SEQ];
static __device__ float g_y      [T_SEQ * C_EMB];
static __device__ float g_x2     [T_SEQ * C_EMB];
static __device__ float g_n2     [T_SEQ * C_EMB];
static __device__ float g_gate   [T_SEQ * FFN_N];
static __device__ float g_up     [T_SEQ * FFN_N];
static __device__ float g_act    [T_SEQ * FFN_N];

__device__ __forceinline__ float warpReduceSum(float v) {
    #pragma unroll
    for (int o = 16; o > 0; o >>= 1) v += __shfl_xor_sync(0xffffffffu, v, o);
    return v;
}
__device__ __forceinline__ float warpReduceMax(float v) {
    #pragma unroll
    for (int o = 16; o > 0; o >>= 1) v = fmaxf(v, __shfl_xor_sync(0xffffffffu, v, o));
    return v;
}

// ---------------------------------------------------------------------------
// rmsnorm
// ---------------------------------------------------------------------------
__global__ void rmsnorm_kernel(const float* __restrict__ x,
                               const float* __restrict__ w,
                               float* __restrict__ out) {
    int row = blockIdx.x;
    const float* xr = x + (size_t)row * C_EMB;
    float* orow = out + (size_t)row * C_EMB;
    int tid = threadIdx.x;
    float ss = 0.f;
    for (int i = tid; i < C_EMB; i += 256) { float v = xr[i]; ss += v * v; }
    __shared__ float sm[8];
    __shared__ float s_inv;
    float ws = warpReduceSum(ss);
    if ((tid & 31) == 0) sm[tid >> 5] = ws;
    __syncthreads();
    if (tid == 0) {
        float tot = 0.f;
        #pragma unroll
        for (int i = 0; i < 8; i++) tot += sm[i];
        s_inv = rsqrtf(tot / (float)C_EMB + EPS);
    }
    __syncthreads();
    float inv = s_inv;
    for (int i = tid; i < C_EMB; i += 256) orow[i] = xr[i] * inv * w[i];
}

// ---------------------------------------------------------------------------
// Split GEMM, templated N-tile (128/64) and MODE:
//   MODE 0: bf16 3-pass (A,B both split hi/lo; passes hh, lh, hl)
//   MODE 1: fp16 2-pass (A split hi/lo fp16; B single fp16; passes ah*b, al*b)
// C[m][n] = sum_k A[m][k]*B[n][k] (+res). Tiles with bn >= N1 switch to
// (B2, C2, ldc2) (fuses two same-A GEMMs). Depth-2 LDG pipeline.
// ---------------------------------------------------------------------------
#define BM 128
#define BK 16
#define PITCH 24   // uint16 elems per smem row: 48B, conflict-free (12r+q mod 32)

__device__ __forceinline__ void split2(float x0, float x1, uint32_t& h, uint32_t& l) {
    asm("cvt.rn.bf16x2.f32 %0, %1, %2;" : "=r"(h) : "f"(x1), "f"(x0));
    float f0 = __uint_as_float(h << 16);
    float f1 = __uint_as_float(h & 0xffff0000u);
    asm("cvt.rn.bf16x2.f32 %0, %1, %2;" : "=r"(l) : "f"(x1 - f1), "f"(x0 - f0));
}
__device__ __forceinline__ void store_split(uint16_t* hrow, uint16_t* lrow, float4 v) {
    uint32_t h0, l0, h1, l1;
    split2(v.x, v.y, h0, l0);
    split2(v.z, v.w, h1, l1);
    *(uint64_t*)hrow = ((uint64_t)h1 << 32) | h0;
    *(uint64_t*)lrow = ((uint64_t)l1 << 32) | l0;
}
__device__ __forceinline__ void split2h(float x0, float x1, uint32_t& h, uint32_t& l) {
    __half2 hh = __floats2half2_rn(x0, x1);
    float2 fb = __half22float2(hh);
    __half2 ll = __floats2half2_rn(x0 - fb.x, x1 - fb.y);
    h = *(uint32_t*)&hh;
    l = *(uint32_t*)&ll;
}
__device__ __forceinline__ void store_split_h(uint16_t* hrow, uint16_t* lrow, float4 v) {
    uint32_t h0, l0, h1, l1;
    split2h(v.x, v.y, h0, l0);
    split2h(v.z, v.w, h1, l1);
    *(uint64_t*)hrow = ((uint64_t)h1 << 32) | h0;
    *(uint64_t*)lrow = ((uint64_t)l1 << 32) | l0;
}
__device__ __forceinline__ void store_h16(uint16_t* row, float4 v) {
    __half2 h0 = __floats2half2_rn(v.x, v.y);
    __half2 h1 = __floats2half2_rn(v.z, v.w);
    *(uint64_t*)row = ((uint64_t)(*(uint32_t*)&h1) << 32) | (*(uint32_t*)&h0);
}
__device__ __forceinline__ void mma_bf16(float* c, const uint32_t* a, const uint32_t* b) {
    asm volatile(
        "mma.sync.aligned.m16n8k16.row.col.f32.bf16.bf16.f32 "
        "{%0,%1,%2,%3}, {%4,%5,%6,%7}, {%8,%9}, {%0,%1,%2,%3};\n"
        : "+f"(c[0]), "+f"(c[1]), "+f"(c[2]), "+f"(c[3])
        : "r"(a[0]), "r"(a[1]), "r"(a[2]), "r"(a[3]), "r"(b[0]), "r"(b[1]));
}
__device__ __forceinline__ void mma_f16(float* c, const uint32_t* a, const uint32_t* b) {
    asm volatile(
        "mma.sync.aligned.m16n8k16.row.col.f32.f16.f16.f32 "
        "{%0,%1,%2,%3}, {%4,%5,%6,%7}, {%8,%9}, {%0,%1,%2,%3};\n"
        : "+f"(c[0]), "+f"(c[1]), "+f"(c[2]), "+f"(c[3])
        : "r"(a[0]), "r"(a[1]), "r"(a[2]), "r"(a[3]), "r"(b[0]), "r"(b[1]));
}

template <int BNT, int MODE>
__global__ __launch_bounds__(256, 1)
void gemm_sp(const float* __restrict__ A,
             const float* __restrict__ B,
             const float* __restrict__ B2,
             const float* __restrict__ Dres,
             float* __restrict__ C,
             float* __restrict__ C2,
             int N1, int K, int lda, int ldb, int ldc, int ldc2,
             long long sA, long long sB, long long sC, int bdiv) {
    constexpr int NJ = BNT / 16;          // b-fragments per warp
    constexpr int BJ = BNT / 64;          // B fill iterations
    constexpr int BC = (MODE == 1) ? 1 : 2;
    __shared__ __align__(16) uint16_t smA[2][2][BM][PITCH];
    __shared__ __align__(16) uint16_t smB[2][BC][BNT][PITCH];

    int bn = blockIdx.x * BNT;
    if (N1 > 0 && bn >= N1) { B = B2; C = C2; ldc = ldc2; bn -= N1; }

    int z = blockIdx.z;
    A += (long long)z * sA;
    B += (long long)(z / bdiv) * sB;
    C += (long long)z * sC;
    if (Dres) Dres += (long long)z * sC;

    const int bm = blockIdx.y * BM;
    const int tid  = threadIdx.x;
    const int lane = tid & 31;
    const int warp = tid >> 5;
    const int wm = (warp & 3) * 32;
    const int wn = (warp >> 2) * (BNT / 2);
    const int grp = lane >> 2;
    const int qid = lane & 3;

    const int frow = tid >> 2;
    const int fkq  = (tid & 3) * 4;

    const float* AgP[2];
    AgP[0] = A + (size_t)(bm + frow) * lda + fkq;
    AgP[1] = A + (size_t)(bm + frow + 64) * lda + fkq;
    const float* BgP[2];
    BgP[0] = B + (size_t)(bn + frow) * ldb + fkq;
    BgP[1] = (BJ == 2) ? (B + (size_t)(bn + frow + 64) * ldb + fkq) : BgP[0];

    float acc[2][NJ][4];
    #pragma unroll
    for (int mi = 0; mi < 2; mi++)
        #pragma unroll
        for (int nj = 0; nj < NJ; nj++)
            #pragma unroll
            for (int q = 0; q < 4; q++) acc[mi][nj][q] = 0.f;

    const int nk = K / BK;

    // store helpers (MODE-dependent)
    #define ST_A(buf, row, v) do {                                            \
        if (MODE == 0) store_split(&smA[buf][0][row][fkq], &smA[buf][1][row][fkq], v); \
        else           store_split_h(&smA[buf][0][row][fkq], &smA[buf][1][row][fkq], v); \
    } while (0)
    #define ST_B(buf, row, v) do {                                            \
        if (MODE == 0) store_split(&smB[buf][0][row][fkq], &smB[buf][BC-1][row][fkq], v); \
        else           store_h16(&smB[buf][0][row][fkq], v);                  \
    } while (0)

    // chunk 0 -> smem buf0
    {
        #pragma unroll
        for (int j = 0; j < 2; j++) {
            float4 v = *(const float4*)(AgP[j]);
            ST_A(0, frow + 64 * j, v);
        }
        #pragma unroll
        for (int j = 0; j < BJ; j++) {
            float4 v = *(const float4*)(BgP[j]);
            ST_B(0, frow + 64 * j, v);
        }
    }
    // chunk 1 -> registers L1
    float4 L1a[2], L1b[BJ];
    if (nk > 1) {
        #pragma unroll
        for (int j = 0; j < 2; j++) L1a[j] = *(const float4*)(AgP[j] + BK);
        #pragma unroll
        for (int j = 0; j < BJ; j++) L1b[j] = *(const float4*)(BgP[j] + BK);
    }
    __syncthreads();

    for (int kt = 0; kt < nk; kt++) {
        const int cur = kt & 1;
        const int nxt = cur ^ 1;

        float4 L2a[2], L2b[BJ];
        if (kt + 2 < nk) {
            const int ko = (kt + 2) * BK;
            #pragma unroll
            for (int j = 0; j < 2; j++) L2a[j] = *(const float4*)(AgP[j] + ko);
            #pragma unroll
            for (int j = 0; j < BJ; j++) L2b[j] = *(const float4*)(BgP[j] + ko);
        }

        uint32_t ah[2][4], al[2][4], bh[NJ][2], bl[NJ][2];
        #pragma unroll
        for (int mi = 0; mi < 2; mi++) {
            int m0 = wm + mi * 16 + grp;
            int m1 = m0 + 8;
            int k0 = 2 * qid, k1 = 8 + 2 * qid;
            ah[mi][0] = *(const uint32_t*)&smA[cur][0][m0][k0];
            ah[mi][1] = *(const uint32_t*)&smA[cur][0][m1][k0];
            ah[mi][2] = *(const uint32_t*)&smA[cur][0][m0][k1];
            ah[mi][3] = *(const uint32_t*)&smA[cur][0][m1][k1];
            al[mi][0] = *(const uint32_t*)&smA[cur][1][m0][k0];
            al[mi][1] = *(const uint32_t*)&smA[cur][1][m1][k0];
            al[mi][2] = *(const uint32_t*)&smA[cur][1][m0][k1];
            al[mi][3] = *(const uint32_t*)&smA[cur][1][m1][k1];
        }
        #pragma unroll
        for (int nj = 0; nj < NJ; nj++) {
            int n = wn + nj * 8 + grp;
            int k0 = 2 * qid, k1 = 8 + 2 * qid;
            bh[nj][0] = *(const uint32_t*)&smB[cur][0][n][k0];
            bh[nj][1] = *(const uint32_t*)&smB[cur][0][n][k1];
            if (MODE == 0) {
                bl[nj][0] = *(const uint32_t*)&smB[cur][BC - 1][n][k0];
                bl[nj][1] = *(const uint32_t*)&smB[cur][BC - 1][n][k1];
            }
        }

        if (MODE == 0) {
            #pragma unroll
            for (int mi = 0; mi < 2; mi++)
                #pragma unroll
                for (int nj = 0; nj < NJ; nj++)
                    mma_bf16(acc[mi][nj], ah[mi], bh[nj]);
            #pragma unroll
            for (int mi = 0; mi < 2; mi++)
                #pragma unroll
                for (int nj = 0; nj < NJ; nj++)
                    mma_bf16(acc[mi][nj], al[mi], bh[nj]);
            #pragma unroll
            for (int mi = 0; mi < 2; mi++)
                #pragma unroll
                for (int nj = 0; nj < NJ; nj++)
                    mma_bf16(acc[mi][nj], ah[mi], bl[nj]);
        } else {
            #pragma unroll
            for (int mi = 0; mi < 2; mi++)
                #pragma unroll
                for (int nj = 0; nj < NJ; nj++)
                    mma_f16(acc[mi][nj], ah[mi], bh[nj]);
            #pragma unroll
            for (int mi = 0; mi < 2; mi++)
                #pragma unroll
                for (int nj = 0; nj < NJ; nj++)
                    mma_f16(acc[mi][nj], al[mi], bh[nj]);
        }

        if (kt + 1 < nk) {
            #pragma unroll
            for (int j = 0; j < 2; j++) ST_A(nxt, frow + 64 * j, L1a[j]);
            #pragma unroll
            for (int j = 0; j < BJ; j++) ST_B(nxt, frow + 64 * j, L1b[j]);
        }
        if (kt + 2 < nk) {
            #pragma unroll
            for (int j = 0; j < 2; j++) L1a[j] = L2a[j];
            #pragma unroll
            for (int j = 0; j < BJ; j++) L1b[j] = L2b[j];
        }
        __syncthreads();
    }

    #pragma unroll
    for (int mi = 0; mi < 2; mi++) {
        #pragma unroll
        for (int nj = 0; nj < NJ; nj++) {
            int row = bm + wm + mi * 16 + grp;
            int col = bn + wn + nj * 8 + qid * 2;
            size_t i0 = (size_t)row * ldc + col;
            size_t i1 = (size_t)(row + 8) * ldc + col;
            float v0 = acc[mi][nj][0], v1 = acc[mi][nj][1];
            float v2 = acc[mi][nj][2], v3 = acc[mi][nj][3];
            if (Dres) {
                v0 += Dres[i0]; v1 += Dres[i0 + 1];
                v2 += Dres[i1]; v3 += Dres[i1 + 1];
            }
            C[i0] = v0; C[i0 + 1] = v1;
            C[i1] = v2; C[i1 + 1] = v3;
        }
    }
}

// ---------------------------------------------------------------------------
// qkv split + rope (v transposed)
// ---------------------------------------------------------------------------
__global__ void qkv_rope_split_kernel(const float* __restrict__ qkv,
                                      const float* __restrict__ cos_,
                                      const float* __restrict__ sin_,
                                      float* __restrict__ q,
                                      float* __restrict__ k,
                                      float* __restrict__ vT) {
    int idx = blockIdx.x * 256 + threadIdx.x;
    if (idx >= T_SEQ * QKV_N) return;
    int t = idx / QKV_N;
    int c = idx - t * QKV_N;
    int g = c / (6 * HS);
    int rem = c - g * 6 * HS;
    int slot = rem / HS;
    int d = rem - slot * HS;
    float val = qkv[idx];
    if (slot < 5) {
        int hb = idx - d;
        float partner = (d < 64) ? -qkv[hb + d + 64] : qkv[hb + d - 64];
        val = val * cos_[t * HS + d] + partner * sin_[t * HS + d];
    }
    if (slot < 4)       q[((size_t)(g * 4 + slot) * T_SEQ + t) * HS + d] = val;
    else if (slot == 4) k[((size_t)g * T_SEQ + t) * HS + d] = val;
    else                vT[((size_t)g * HS + d) * T_SEQ + t] = val;
}

__global__ void scale_reduce_kernel(const float* __restrict__ S,
                                    const float* __restrict__ bias,
                                    float* __restrict__ scale_t) {
    int b = blockIdx.x;
    int h = b / T_SEQ;
    int t = b - h * T_SEQ;
    int d = threadIdx.x;
    int c = h * HS + d;
    float vv = fmaxf(S[(size_t)t * C_EMB + c] + bias[c], 0.f);
    __shared__ float sm[4];
    float ws = warpReduceSum(vv);
    if ((d & 31) == 0) sm[d >> 5] = ws;
    __syncthreads();
    if (d == 0) scale_t[b] = SF * ((sm[0] + sm[1] + sm[2] + sm[3]) / (float)HS);
}

__global__ void softmax_kernel(float* __restrict__ S,
                               const float* __restrict__ scale_t) {
    size_t r = blockIdx.x;
    float alpha = scale_t[r];
    float* row = S + r * (size_t)T_SEQ;
    int tid = threadIdx.x;
    float vals[8];
    float m = -INFINITY;
    #pragma unroll
    for (int i = 0; i < 8; i++) {
        vals[i] = alpha * row[tid + 256 * i];
        m = fmaxf(m, vals[i]);
    }
    __shared__ float sm[8];
    __shared__ float s_b;
    float wm = warpReduceMax(m);
    if ((tid & 31) == 0) sm[tid >> 5] = wm;
    __syncthreads();
    if (tid == 0) {
        float mm = sm[0];
        #pragma unroll
        for (int i = 1; i < 8; i++) mm = fmaxf(mm, sm[i]);
        s_b = mm;
    }
    __syncthreads();
    m = s_b;
    float s = 0.f;
    #pragma unroll
    for (int i = 0; i < 8; i++) { vals[i] = __expf(vals[i] - m); s += vals[i]; }
    __syncthreads();
    float ws = warpReduceSum(s);
    if ((tid & 31) == 0) sm[tid >> 5] = ws;
    __syncthreads();
    if (tid == 0) {
        float tot = 0.f;
        #pragma unroll
        for (int i = 0; i < 8; i++) tot += sm[i];
        s_b = 1.f / tot;
    }
    __syncthreads();
    float inv = s_b;
    #pragma unroll
    for (int i = 0; i < 8; i++) row[tid + 256 * i] = vals[i] * inv;
}

__global__ void silu_mul_kernel(const float* __restrict__ g,
                                const float* __restrict__ u,
                                float* __restrict__ out, int n) {
    int idx = blockIdx.x * 256 + threadIdx.x;
    if (idx >= n) return;
    float x = g[idx];
    out[idx] = x / (1.f + __expf(-x)) * u[idx];
}

// ---------------------------------------------------------------------------
extern "C" void kernel_launch(void* const* d_in, const int* in_sizes, int n_in,
                              void* d_out, int out_size) {
    const float* x       = (const float*)d_in[0];
    const float* cosp    = (const float*)d_in[1];
    const float* sinp    = (const float*)d_in[2];
    const float* norm1_w = (const float*)d_in[3];
    const float* norm2_w = (const float*)d_in[4];
    const float* attn_w  = (const float*)d_in[5];
    const float* proj_w  = (const float*)d_in[6];
    const float* scale_w = (const float*)d_in[7];
    const float* scale_b = (const float*)d_in[8];
    const float* gate_w  = (const float*)d_in[9];
    const float* up_w    = (const float*)d_in[10];
    const float* down_w  = (const float*)d_in[11];
    float* out = (float*)d_out;

    float *n1, *qkv, *scaleS, *scale_t, *q, *k, *vT, *S, *y, *x2, *n2, *gate, *up, *act;
    cudaGetSymbolAddress((void**)&n1, g_n1);
    cudaGetSymbolAddress((void**)&qkv, g_qkv);
    cudaGetSymbolAddress((void**)&scaleS, g_scaleS);
    cudaGetSymbolAddress((void**)&scale_t, g_scale_t);
    cudaGetSymbolAddress((void**)&q, g_q);
    cudaGetSymbolAddress((void**)&k, g_k);
    cudaGetSymbolAddress((void**)&vT, g_vT);
    cudaGetSymbolAddress((void**)&S, g_S);
    cudaGetSymbolAddress((void**)&y, g_y);
    cudaGetSymbolAddress((void**)&x2, g_x2);
    cudaGetSymbolAddress((void**)&n2, g_n2);
    cudaGetSymbolAddress((void**)&gate, g_gate);
    cudaGetSymbolAddress((void**)&up, g_up);
    cudaGetSymbolAddress((void**)&act, g_act);

    rmsnorm_kernel<<<T_SEQ, 256>>>(x, norm1_w, n1);

    // fused qkv | scaleS (bf16 3-pass: score-path accuracy)
    gemm_sp<128, 0><<<dim3((QKV_N + C_EMB) / 128, T_SEQ / BM, 1), 256>>>(
        n1, attn_w, scale_w, nullptr, qkv, scaleS,
        QKV_N, C_EMB, C_EMB, C_EMB, QKV_N, C_EMB, 0, 0, 0, 1);

    scale_reduce_kernel<<<NH * T_SEQ, 128>>>(scaleS, scale_b, scale_t);

    qkv_rope_split_kernel<<<(T_SEQ * QKV_N + 255) / 256, 256>>>(qkv, cosp, sinp, q, k, vT);

    // scores (bf16 3-pass)
    gemm_sp<128, 0><<<dim3(T_SEQ / 128, T_SEQ / BM, NH), 256>>>(
        q, k, nullptr, nullptr, S, nullptr,
        0, HS, HS, HS, T_SEQ, 0,
        (long long)T_SEQ * HS, (long long)T_SEQ * HS, (long long)T_SEQ * T_SEQ, 4);

    softmax_kernel<<<NH * T_SEQ, 256>>>(S, scale_t);

    // AV (bf16 3-pass, BN=64)
    gemm_sp<64, 0><<<dim3(HS / 64, T_SEQ / BM, NH), 256>>>(
        S, vT, nullptr, nullptr, y, nullptr,
        0, T_SEQ, T_SEQ, T_SEQ, C_EMB, 0,
        (long long)T_SEQ * T_SEQ, (long long)HS * T_SEQ, (long long)HS, 4);

    // proj + residual (fp16 2-pass, BN=64)
    gemm_sp<64, 1><<<dim3(C_EMB / 64, T_SEQ / BM, 1), 256>>>(
        y, proj_w, nullptr, x, x2, nullptr,
        0, C_EMB, C_EMB, C_EMB, C_EMB, 0, 0, 0, 0, 1);

    rmsnorm_kernel<<<T_SEQ, 256>>>(x2, norm2_w, n2);

    // fused gate | up (fp16 2-pass)
    gemm_sp<128, 1><<<dim3(2 * FFN_N / 128, T_SEQ / BM, 1), 256>>>(
        n2, gate_w, up_w, nullptr, gate, up,
        FFN_N, C_EMB, C_EMB, C_EMB, FFN_N, FFN_N, 0, 0, 0, 1);

    silu_mul_kernel<<<(T_SEQ * FFN_N + 255) / 256, 256>>>(gate, up, act, T_SEQ * FFN_N);

    // down + residual (fp16 2-pass, BN=64)
    gemm_sp<64, 1><<<dim3(C_EMB / 64, T_SEQ / BM, 1), 256>>>(
        act, down_w, nullptr, x2, out, nullptr,
        0, FFN_N, FFN_N, FFN_N, C_EMB, 0, 0, 0, 0, 1);
}

// round 16
// speedup vs baseline: 2.8221x; 1.0640x over previous
#include <cuda_runtime.h>
#include <cuda_fp16.h>
#include <math.h>
#include <stdint.h>

#define T_SEQ 2048
#define C_EMB 4096
#define NH    32
#define NG    8
#define HS    128
#define QKV_N 6144
#define FFN_N 11008
#define EPS   1e-5f
#define SF    0.08838834764831845f

static __device__ float  g_n1     [T_SEQ * C_EMB];
static __device__ float  g_qkv    [T_SEQ * QKV_N];
static __device__ float  g_scaleS [T_SEQ * C_EMB];
static __device__ float  g_scale_t[NH * T_SEQ];
static __device__ float  g_q      [NH * T_SEQ * HS];
static __device__ float  g_k      [NG * T_SEQ * HS];
static __device__ float  g_vT     [NG * HS * T_SEQ];
static __device__ float  g_S      [(size_t)NH * T_SEQ * T_SEQ];
static __device__ __half g_P      [(size_t)NH * T_SEQ * T_SEQ];
static __device__ __half g_yh     [T_SEQ * C_EMB];
static __device__ float  g_x2     [T_SEQ * C_EMB];
static __device__ float  g_n2     [T_SEQ * C_EMB];
static __device__ float  g_gate   [T_SEQ * FFN_N];
static __device__ float  g_up     [T_SEQ * FFN_N];
static __device__ __half g_act    [T_SEQ * FFN_N];

__device__ __forceinline__ float warpReduceSum(float v) {
    #pragma unroll
    for (int o = 16; o > 0; o >>= 1) v += __shfl_xor_sync(0xffffffffu, v, o);
    return v;
}
__device__ __forceinline__ float warpReduceMax(float v) {
    #pragma unroll
    for (int o = 16; o > 0; o >>= 1) v = fmaxf(v, __shfl_xor_sync(0xffffffffu, v, o));
    return v;
}

// ---------------------------------------------------------------------------
// rmsnorm
// ---------------------------------------------------------------------------
__global__ void rmsnorm_kernel(const float* __restrict__ x,
                               const float* __restrict__ w,
                               float* __restrict__ out) {
    int row = blockIdx.x;
    const float* xr = x + (size_t)row * C_EMB;
    float* orow = out + (size_t)row * C_EMB;
    int tid = threadIdx.x;
    float ss = 0.f;
    for (int i = tid; i < C_EMB; i += 256) { float v = xr[i]; ss += v * v; }
    __shared__ float sm[8];
    __shared__ float s_inv;
    float ws = warpReduceSum(ss);
    if ((tid & 31) == 0) sm[tid >> 5] = ws;
    __syncthreads();
    if (tid == 0) {
        float tot = 0.f;
        #pragma unroll
        for (int i = 0; i < 8; i++) tot += sm[i];
        s_inv = rsqrtf(tot / (float)C_EMB + EPS);
    }
    __syncthreads();
    float inv = s_inv;
    for (int i = tid; i < C_EMB; i += 256) orow[i] = xr[i] * inv * w[i];
}

// ---------------------------------------------------------------------------
// Split GEMM. C[m][n] = sum_k A[m][k]*B[n][k] (+res).
// MODE 0: A,B fp32->bf16 split; 3 passes (hh, lh, hl)            [bf16 mma]
// MODE 1: A fp32->fp16 split; B fp32->fp16 single; 2 passes      [f16 mma]
// MODE 2: A fp16 source (single); B fp32->fp16 split; 2 passes   [f16 mma]
// MODE 3: A fp16 source (single); B fp32->fp16 single; 1 pass    [f16 mma]
// OUTH: epilogue writes __half (no residual support).
// Tiles with bn >= N1 switch to (B2, C2, ldc2). Depth-2 LDG pipeline.
// ---------------------------------------------------------------------------
#define BM 128
#define BK 16
#define PITCH 24   // uint16 elems per smem row: 48B, conflict-free

__device__ __forceinline__ void split2(float x0, float x1, uint32_t& h, uint32_t& l) {
    asm("cvt.rn.bf16x2.f32 %0, %1, %2;" : "=r"(h) : "f"(x1), "f"(x0));
    float f0 = __uint_as_float(h << 16);
    float f1 = __uint_as_float(h & 0xffff0000u);
    asm("cvt.rn.bf16x2.f32 %0, %1, %2;" : "=r"(l) : "f"(x1 - f1), "f"(x0 - f0));
}
__device__ __forceinline__ void store_split(uint16_t* hrow, uint16_t* lrow, float4 v) {
    uint32_t h0, l0, h1, l1;
    split2(v.x, v.y, h0, l0);
    split2(v.z, v.w, h1, l1);
    *(uint64_t*)hrow = ((uint64_t)h1 << 32) | h0;
    *(uint64_t*)lrow = ((uint64_t)l1 << 32) | l0;
}
__device__ __forceinline__ void split2h(float x0, float x1, uint32_t& h, uint32_t& l) {
    __half2 hh = __floats2half2_rn(x0, x1);
    float2 fb = __half22float2(hh);
    __half2 ll = __floats2half2_rn(x0 - fb.x, x1 - fb.y);
    h = *(uint32_t*)&hh;
    l = *(uint32_t*)&ll;
}
__device__ __forceinline__ void store_split_h(uint16_t* hrow, uint16_t* lrow, float4 v) {
    uint32_t h0, l0, h1, l1;
    split2h(v.x, v.y, h0, l0);
    split2h(v.z, v.w, h1, l1);
    *(uint64_t*)hrow = ((uint64_t)h1 << 32) | h0;
    *(uint64_t*)lrow = ((uint64_t)l1 << 32) | l0;
}
__device__ __forceinline__ void store_h16(uint16_t* row, float4 v) {
    __half2 h0 = __floats2half2_rn(v.x, v.y);
    __half2 h1 = __floats2half2_rn(v.z, v.w);
    *(uint64_t*)row = ((uint64_t)(*(uint32_t*)&h1) << 32) | (*(uint32_t*)&h0);
}
__device__ __forceinline__ void mma_bf16(float* c, const uint32_t* a, const uint32_t* b) {
    asm volatile(
        "mma.sync.aligned.m16n8k16.row.col.f32.bf16.bf16.f32 "
        "{%0,%1,%2,%3}, {%4,%5,%6,%7}, {%8,%9}, {%0,%1,%2,%3};\n"
        : "+f"(c[0]), "+f"(c[1]), "+f"(c[2]), "+f"(c[3])
        : "r"(a[0]), "r"(a[1]), "r"(a[2]), "r"(a[3]), "r"(b[0]), "r"(b[1]));
}
__device__ __forceinline__ void mma_f16(float* c, const uint32_t* a, const uint32_t* b) {
    asm volatile(
        "mma.sync.aligned.m16n8k16.row.col.f32.f16.f16.f32 "
        "{%0,%1,%2,%3}, {%4,%5,%6,%7}, {%8,%9}, {%0,%1,%2,%3};\n"
        : "+f"(c[0]), "+f"(c[1]), "+f"(c[2]), "+f"(c[3])
        : "r"(a[0]), "r"(a[1]), "r"(a[2]), "r"(a[3]), "r"(b[0]), "r"(b[1]));
}

template <int BNT, int MODE, int OUTH>
__global__ __launch_bounds__(256, 1)
void gemm_sp(const void* __restrict__ Ap,
             const float* __restrict__ B,
             const float* __restrict__ B2,
             const float* __restrict__ Dres,
             void* __restrict__ Cp,
             void* __restrict__ C2p,
             int N1, int K, int lda, int ldb, int ldc, int ldc2,
             long long sA, long long sB, long long sC, int bdiv) {
    constexpr bool AHALF  = (MODE >= 2);
    constexpr bool ASPLIT = (MODE <= 1);
    constexpr bool BSPLIT = (MODE == 0 || MODE == 2);
    constexpr int AP_ = ASPLIT ? 2 : 1;
    constexpr int BP_ = BSPLIT ? 2 : 1;
    constexpr int NJ = BNT / 16;
    constexpr int BJ = BNT / 64;
    __shared__ __align__(16) uint16_t smA[2][AP_][BM][PITCH];
    __shared__ __align__(16) uint16_t smB[2][BP_][BNT][PITCH];

    int bn = blockIdx.x * BNT;
    void* Cv = Cp;
    if (N1 > 0 && bn >= N1) { B = B2; Cv = C2p; ldc = ldc2; bn -= N1; }

    int z = blockIdx.z;
    const float*  A32 = (const float*)Ap + (AHALF ? 0 : (long long)z * sA);
    const __half* A16 = (const __half*)Ap + (AHALF ? (long long)z * sA : 0);
    B += (long long)(z / bdiv) * sB;
    float*  Cf = (float*)Cv + (OUTH ? 0 : (long long)z * sC);
    __half* Ch = (__half*)Cv + (OUTH ? (long long)z * sC : 0);
    if (Dres) Dres += (long long)z * sC;

    const int bm = blockIdx.y * BM;
    const int tid  = threadIdx.x;
    const int lane = tid & 31;
    const int warp = tid >> 5;
    const int wm = (warp & 3) * 32;
    const int wn = (warp >> 2) * (BNT / 2);
    const int grp = lane >> 2;
    const int qid = lane & 3;

    // fp32-A / B fill mapping
    const int frow = tid >> 2;
    const int fkq  = (tid & 3) * 4;
    // fp16-A fill mapping
    const int hrow = tid >> 1;
    const int hseg = (tid & 1) * 8;

    const float* AgP[2];
    if (!AHALF) {
        AgP[0] = A32 + (size_t)(bm + frow) * lda + fkq;
        AgP[1] = A32 + (size_t)(bm + frow + 64) * lda + fkq;
    }
    const __half* Ag16 = AHALF ? (A16 + (size_t)(bm + hrow) * lda + hseg) : (const __half*)0;
    const float* BgP[2];
    BgP[0] = B + (size_t)(bn + frow) * ldb + fkq;
    BgP[1] = (BJ == 2) ? (B + (size_t)(bn + frow + 64) * ldb + fkq) : BgP[0];

    float acc[2][NJ][4];
    #pragma unroll
    for (int mi = 0; mi < 2; mi++)
        #pragma unroll
        for (int nj = 0; nj < NJ; nj++)
            #pragma unroll
            for (int q = 0; q < 4; q++) acc[mi][nj][q] = 0.f;

    const int nk = K / BK;

    #define ST_A32(buf, row, v) do {                                          \
        if (MODE == 0) store_split(&smA[buf][0][row][fkq], &smA[buf][AP_-1][row][fkq], v); \
        else           store_split_h(&smA[buf][0][row][fkq], &smA[buf][AP_-1][row][fkq], v); \
    } while (0)
    #define ST_B(buf, row, v) do {                                            \
        if (MODE == 0)      store_split(&smB[buf][0][row][fkq], &smB[buf][BP_-1][row][fkq], v); \
        else if (MODE == 2) store_split_h(&smB[buf][0][row][fkq], &smB[buf][BP_-1][row][fkq], v); \
        else                store_h16(&smB[buf][0][row][fkq], v);             \
    } while (0)

    // chunk 0 -> smem buf0
    if (!AHALF) {
        #pragma unroll
        for (int j = 0; j < 2; j++) {
            float4 v = *(const float4*)(AgP[j]);
            ST_A32(0, frow + 64 * j, v);
        }
    } else {
        uint4 v = *(const uint4*)(Ag16);
        *(uint4*)&smA[0][0][hrow][hseg] = v;
    }
    #pragma unroll
    for (int j = 0; j < BJ; j++) {
        float4 v = *(const float4*)(BgP[j]);
        ST_B(0, frow + 64 * j, v);
    }
    // chunk 1 -> registers L1
    float4 L1a[2]; uint4 L1ah; float4 L1b[2];
    if (nk > 1) {
        if (!AHALF) {
            #pragma unroll
            for (int j = 0; j < 2; j++) L1a[j] = *(const float4*)(AgP[j] + BK);
        } else {
            L1ah = *(const uint4*)(Ag16 + BK);
        }
        #pragma unroll
        for (int j = 0; j < BJ; j++) L1b[j] = *(const float4*)(BgP[j] + BK);
    }
    __syncthreads();

    for (int kt = 0; kt < nk; kt++) {
        const int cur = kt & 1;
        const int nxt = cur ^ 1;

        float4 L2a[2]; uint4 L2ah; float4 L2b[2];
        if (kt + 2 < nk) {
            const int ko = (kt + 2) * BK;
            if (!AHALF) {
                #pragma unroll
                for (int j = 0; j < 2; j++) L2a[j] = *(const float4*)(AgP[j] + ko);
            } else {
                L2ah = *(const uint4*)(Ag16 + ko);
            }
            #pragma unroll
            for (int j = 0; j < BJ; j++) L2b[j] = *(const float4*)(BgP[j] + ko);
        }

        uint32_t ah[2][4], al[2][4], bh[NJ][2], bl[NJ][2];
        #pragma unroll
        for (int mi = 0; mi < 2; mi++) {
            int m0 = wm + mi * 16 + grp;
            int m1 = m0 + 8;
            int k0 = 2 * qid, k1 = 8 + 2 * qid;
            ah[mi][0] = *(const uint32_t*)&smA[cur][0][m0][k0];
            ah[mi][1] = *(const uint32_t*)&smA[cur][0][m1][k0];
            ah[mi][2] = *(const uint32_t*)&smA[cur][0][m0][k1];
            ah[mi][3] = *(const uint32_t*)&smA[cur][0][m1][k1];
            if (ASPLIT) {
                al[mi][0] = *(const uint32_t*)&smA[cur][AP_-1][m0][k0];
                al[mi][1] = *(const uint32_t*)&smA[cur][AP_-1][m1][k0];
                al[mi][2] = *(const uint32_t*)&smA[cur][AP_-1][m0][k1];
                al[mi][3] = *(const uint32_t*)&smA[cur][AP_-1][m1][k1];
            }
        }
        #pragma unroll
        for (int nj = 0; nj < NJ; nj++) {
            int n = wn + nj * 8 + grp;
            int k0 = 2 * qid, k1 = 8 + 2 * qid;
            bh[nj][0] = *(const uint32_t*)&smB[cur][0][n][k0];
            bh[nj][1] = *(const uint32_t*)&smB[cur][0][n][k1];
            if (BSPLIT) {
                bl[nj][0] = *(const uint32_t*)&smB[cur][BP_-1][n][k0];
                bl[nj][1] = *(const uint32_t*)&smB[cur][BP_-1][n][k1];
            }
        }

        if (MODE == 0) {
            #pragma unroll
            for (int mi = 0; mi < 2; mi++)
                #pragma unroll
                for (int nj = 0; nj < NJ; nj++)
                    mma_bf16(acc[mi][nj], ah[mi], bh[nj]);
            #pragma unroll
            for (int mi = 0; mi < 2; mi++)
                #pragma unroll
                for (int nj = 0; nj < NJ; nj++)
                    mma_bf16(acc[mi][nj], al[mi], bh[nj]);
            #pragma unroll
            for (int mi = 0; mi < 2; mi++)
                #pragma unroll
                for (int nj = 0; nj < NJ; nj++)
                    mma_bf16(acc[mi][nj], ah[mi], bl[nj]);
        } else {
            #pragma unroll
            for (int mi = 0; mi < 2; mi++)
                #pragma unroll
                for (int nj = 0; nj < NJ; nj++)
                    mma_f16(acc[mi][nj], ah[mi], bh[nj]);
            if (MODE == 1) {
                #pragma unroll
                for (int mi = 0; mi < 2; mi++)
                    #pragma unroll
                    for (int nj = 0; nj < NJ; nj++)
                        mma_f16(acc[mi][nj], al[mi], bh[nj]);
            }
            if (MODE == 2) {
                #pragma unroll
                for (int mi = 0; mi < 2; mi++)
                    #pragma unroll
                    for (int nj = 0; nj < NJ; nj++)
                        mma_f16(acc[mi][nj], ah[mi], bl[nj]);
            }
        }

        if (kt + 1 < nk) {
            if (!AHALF) {
                #pragma unroll
                for (int j = 0; j < 2; j++) ST_A32(nxt, frow + 64 * j, L1a[j]);
            } else {
                *(uint4*)&smA[nxt][0][hrow][hseg] = L1ah;
            }
            #pragma unroll
            for (int j = 0; j < BJ; j++) ST_B(nxt, frow + 64 * j, L1b[j]);
        }
        if (kt + 2 < nk) {
            if (!AHALF) {
                #pragma unroll
                for (int j = 0; j < 2; j++) L1a[j] = L2a[j];
            } else {
                L1ah = L2ah;
            }
            #pragma unroll
            for (int j = 0; j < BJ; j++) L1b[j] = L2b[j];
        }
        __syncthreads();
    }

    #pragma unroll
    for (int mi = 0; mi < 2; mi++) {
        #pragma unroll
        for (int nj = 0; nj < NJ; nj++) {
            int row = bm + wm + mi * 16 + grp;
            int col = bn + wn + nj * 8 + qid * 2;
            size_t i0 = (size_t)row * ldc + col;
            size_t i1 = (size_t)(row + 8) * ldc + col;
            float v0 = acc[mi][nj][0], v1 = acc[mi][nj][1];
            float v2 = acc[mi][nj][2], v3 = acc[mi][nj][3];
            if (OUTH) {
                *(__half2*)&Ch[i0] = __floats2half2_rn(v0, v1);
                *(__half2*)&Ch[i1] = __floats2half2_rn(v2, v3);
            } else {
                if (Dres) {
                    v0 += Dres[i0]; v1 += Dres[i0 + 1];
                    v2 += Dres[i1]; v3 += Dres[i1 + 1];
                }
                Cf[i0] = v0; Cf[i0 + 1] = v1;
                Cf[i1] = v2; Cf[i1 + 1] = v3;
            }
        }
    }
}

// ---------------------------------------------------------------------------
// qkv split + rope (v transposed)
// ---------------------------------------------------------------------------
__global__ void qkv_rope_split_kernel(const float* __restrict__ qkv,
                                      const float* __restrict__ cos_,
                                      const float* __restrict__ sin_,
                                      float* __restrict__ q,
                                      float* __restrict__ k,
                                      float* __restrict__ vT) {
    int idx = blockIdx.x * 256 + threadIdx.x;
    if (idx >= T_SEQ * QKV_N) return;
    int t = idx / QKV_N;
    int c = idx - t * QKV_N;
    int g = c / (6 * HS);
    int rem = c - g * 6 * HS;
    int slot = rem / HS;
    int d = rem - slot * HS;
    float val = qkv[idx];
    if (slot < 5) {
        int hb = idx - d;
        float partner = (d < 64) ? -qkv[hb + d + 64] : qkv[hb + d - 64];
        val = val * cos_[t * HS + d] + partner * sin_[t * HS + d];
    }
    if (slot < 4)       q[((size_t)(g * 4 + slot) * T_SEQ + t) * HS + d] = val;
    else if (slot == 4) k[((size_t)g * T_SEQ + t) * HS + d] = val;
    else                vT[((size_t)g * HS + d) * T_SEQ + t] = val;
}

__global__ void scale_reduce_kernel(const float* __restrict__ S,
                                    const float* __restrict__ bias,
                                    float* __restrict__ scale_t) {
    int b = blockIdx.x;
    int h = b / T_SEQ;
    int t = b - h * T_SEQ;
    int d = threadIdx.x;
    int c = h * HS + d;
    float vv = fmaxf(S[(size_t)t * C_EMB + c] + bias[c], 0.f);
    __shared__ float sm[4];
    float ws = warpReduceSum(vv);
    if ((d & 31) == 0) sm[d >> 5] = ws;
    __syncthreads();
    if (d == 0) scale_t[b] = SF * ((sm[0] + sm[1] + sm[2] + sm[3]) / (float)HS);
}

// reads fp32 scores, writes fp16 probabilities
__global__ void softmax_kernel(const float* __restrict__ S,
                               __half* __restrict__ P,
                               const float* __restrict__ scale_t) {
    size_t r = blockIdx.x;
    float alpha = scale_t[r];
    const float* row = S + r * (size_t)T_SEQ;
    __half* prow = P + r * (size_t)T_SEQ;
    int tid = threadIdx.x;
    float vals[8];
    float m = -INFINITY;
    #pragma unroll
    for (int i = 0; i < 8; i++) {
        vals[i] = alpha * row[tid + 256 * i];
        m = fmaxf(m, vals[i]);
    }
    __shared__ float sm[8];
    __shared__ float s_b;
    float wm = warpReduceMax(m);
    if ((tid & 31) == 0) sm[tid >> 5] = wm;
    __syncthreads();
    if (tid == 0) {
        float mm = sm[0];
        #pragma unroll
        for (int i = 1; i < 8; i++) mm = fmaxf(mm, sm[i]);
        s_b = mm;
    }
    __syncthreads();
    m = s_b;
    float s = 0.f;
    #pragma unroll
    for (int i = 0; i < 8; i++) { vals[i] = __expf(vals[i] - m); s += vals[i]; }
    __syncthreads();
    float ws = warpReduceSum(s);
    if ((tid & 31) == 0) sm[tid >> 5] = ws;
    __syncthreads();
    if (tid == 0) {
        float tot = 0.f;
        #pragma unroll
        for (int i = 0; i < 8; i++) tot += sm[i];
        s_b = 1.f / tot;
    }
    __syncthreads();
    float inv = s_b;
    #pragma unroll
    for (int i = 0; i < 8; i++) prow[tid + 256 * i] = __float2half(vals[i] * inv);
}

__global__ void silu_mul_kernel(const float* __restrict__ g,
                                const float* __restrict__ u,
                                __half* __restrict__ out, int n) {
    int idx = blockIdx.x * 256 + threadIdx.x;
    if (idx >= n) return;
    float x = g[idx];
    out[idx] = __float2half(x / (1.f + __expf(-x)) * u[idx]);
}

// ---------------------------------------------------------------------------
extern "C" void kernel_launch(void* const* d_in, const int* in_sizes, int n_in,
                              void* d_out, int out_size) {
    const float* x       = (const float*)d_in[0];
    const float* cosp    = (const float*)d_in[1];
    const float* sinp    = (const float*)d_in[2];
    const float* norm1_w = (const float*)d_in[3];
    const float* norm2_w = (const float*)d_in[4];
    const float* attn_w  = (const float*)d_in[5];
    const float* proj_w  = (const float*)d_in[6];
    const float* scale_w = (const float*)d_in[7];
    const float* scale_b = (const float*)d_in[8];
    const float* gate_w  = (const float*)d_in[9];
    const float* up_w    = (const float*)d_in[10];
    const float* down_w  = (const float*)d_in[11];
    float* out = (float*)d_out;

    float *n1, *qkv, *scaleS, *scale_t, *q, *k, *vT, *S, *x2, *n2, *gate, *up;
    __half *P, *yh, *act;
    cudaGetSymbolAddress((void**)&n1, g_n1);
    cudaGetSymbolAddress((void**)&qkv, g_qkv);
    cudaGetSymbolAddress((void**)&scaleS, g_scaleS);
    cudaGetSymbolAddress((void**)&scale_t, g_scale_t);
    cudaGetSymbolAddress((void**)&q, g_q);
    cudaGetSymbolAddress((void**)&k, g_k);
    cudaGetSymbolAddress((void**)&vT, g_vT);
    cudaGetSymbolAddress((void**)&S, g_S);
    cudaGetSymbolAddress((void**)&P, g_P);
    cudaGetSymbolAddress((void**)&yh, g_yh);
    cudaGetSymbolAddress((void**)&x2, g_x2);
    cudaGetSymbolAddress((void**)&n2, g_n2);
    cudaGetSymbolAddress((void**)&gate, g_gate);
    cudaGetSymbolAddress((void**)&up, g_up);
    cudaGetSymbolAddress((void**)&act, g_act);

    rmsnorm_kernel<<<T_SEQ, 256>>>(x, norm1_w, n1);

    // fused qkv | scaleS (bf16 3-pass)
    gemm_sp<128, 0, 0><<<dim3((QKV_N + C_EMB) / 128, T_SEQ / BM, 1), 256>>>(
        n1, attn_w, scale_w, nullptr, qkv, scaleS,
        QKV_N, C_EMB, C_EMB, C_EMB, QKV_N, C_EMB, 0, 0, 0, 1);

    scale_reduce_kernel<<<NH * T_SEQ, 128>>>(scaleS, scale_b, scale_t);

    qkv_rope_split_kernel<<<(T_SEQ * QKV_N + 255) / 256, 256>>>(qkv, cosp, sinp, q, k, vT);

    // scores (bf16 3-pass)
    gemm_sp<128, 0, 0><<<dim3(T_SEQ / 128, T_SEQ / BM, NH), 256>>>(
        q, k, nullptr, nullptr, S, nullptr,
        0, HS, HS, HS, T_SEQ, 0,
        (long long)T_SEQ * HS, (long long)T_SEQ * HS, (long long)T_SEQ * T_SEQ, 4);

    softmax_kernel<<<NH * T_SEQ, 256>>>(S, P, scale_t);

    // AV: A = P fp16 single, B = vT fp16-split, 2-pass; out yh fp16
    gemm_sp<64, 2, 1><<<dim3(HS / 64, T_SEQ / BM, NH), 256>>>(
        P, vT, nullptr, nullptr, yh, nullptr,
        0, T_SEQ, T_SEQ, T_SEQ, C_EMB, 0,
        (long long)T_SEQ * T_SEQ, (long long)HS * T_SEQ, (long long)HS, 4);

    // proj + residual: A = yh fp16, B = proj_w fp16 single, 1-pass
    gemm_sp<64, 3, 0><<<dim3(C_EMB / 64, T_SEQ / BM, 1), 256>>>(
        yh, proj_w, nullptr, x, x2, nullptr,
        0, C_EMB, C_EMB, C_EMB, C_EMB, 0, 0, 0, 0, 1);

    rmsnorm_kernel<<<T_SEQ, 256>>>(x2, norm2_w, n2);

    // fused gate | up (fp16 2-pass, A split)
    gemm_sp<128, 1, 0><<<dim3(2 * FFN_N / 128, T_SEQ / BM, 1), 256>>>(
        n2, gate_w, up_w, nullptr, gate, up,
        FFN_N, C_EMB, C_EMB, C_EMB, FFN_N, FFN_N, 0, 0, 0, 1);

    silu_mul_kernel<<<(T_SEQ * FFN_N + 255) / 256, 256>>>(gate, up, act, T_SEQ * FFN_N);

    // down + residual: A = act fp16, B = down_w fp16 single, 1-pass
    gemm_sp<64, 3, 0><<<dim3(C_EMB / 64, T_SEQ / BM, 1), 256>>>(
        act, down_w, nullptr, x2, out, nullptr,
        0, FFN_N, FFN_N, FFN_N, C_EMB, 0, 0, 0, 0, 1);
}